// round 1
// baseline (speedup 1.0000x reference)
#include <cuda_runtime.h>
#include <math.h>

#define NH   8
#define HD   64
#define KW   9
#define AA   512
#define HIDD 1024
#define BB   4
#define SS   2048
#define MM   (BB*SS)   // 8192

// ---------------- scratch (device globals; no allocation) ----------------
__device__ float g_q[MM*AA];
__device__ float g_k[MM*AA];
__device__ float g_v[MM*AA];
__device__ float g_col[MM*AA];
__device__ float g_dw[MM*AA];
__device__ float g_ca[MM*AA];
__device__ float g_ckl[MM*NH*KW];

// ---------------- generic SGEMM: C[M,N] = X[M,512] @ W[N,512]^T + bias (opt *mul) ----
// 64x64 tile, BK=16, 256 threads, 4x4 microtile.
__global__ void gemm_kernel(const float* __restrict__ X, int ldx,
                            const float* __restrict__ W, int N,
                            const float* __restrict__ bias,
                            const float* __restrict__ mul, int ldmul,
                            float* __restrict__ C, int ldc)
{
    __shared__ float As[16][64];
    __shared__ float Bs[16][64];
    const int tid = threadIdx.x;
    const int ty = tid >> 4, tx = tid & 15;
    const int bm = blockIdx.y * 64, bn = blockIdx.x * 64;

    float acc[4][4] = {};

    for (int k0 = 0; k0 < 512; k0 += 16) {
        #pragma unroll
        for (int i = 0; i < 4; i++) {
            int idx = tid + i * 256;
            int kk = idx & 15, r = idx >> 4;
            As[kk][r] = X[(size_t)(bm + r) * ldx + k0 + kk];
            int n = bn + r;
            Bs[kk][r] = (n < N) ? W[(size_t)n * 512 + k0 + kk] : 0.f;
        }
        __syncthreads();
        #pragma unroll
        for (int kk = 0; kk < 16; kk++) {
            float4 a4 = *(const float4*)&As[kk][ty * 4];
            float4 b4 = *(const float4*)&Bs[kk][tx * 4];
            float a[4] = {a4.x, a4.y, a4.z, a4.w};
            float b[4] = {b4.x, b4.y, b4.z, b4.w};
            #pragma unroll
            for (int r = 0; r < 4; r++)
                #pragma unroll
                for (int c = 0; c < 4; c++)
                    acc[r][c] = fmaf(a[r], b[c], acc[r][c]);
        }
        __syncthreads();
    }

    #pragma unroll
    for (int r = 0; r < 4; r++) {
        int m = bm + ty * 4 + r;
        #pragma unroll
        for (int c = 0; c < 4; c++) {
            int n = bn + tx * 4 + c;
            if (n < N) {
                float v = acc[r][c] + bias[n];
                if (mul) v *= mul[(size_t)m * ldmul + n];
                C[(size_t)m * ldc + n] = v;
            }
        }
    }
}

// ---------------- depthwise conv along seq (K=9, pad 4), input = conv half of hidden ----
__global__ void dwconv_kernel(const float* __restrict__ hid, const float* __restrict__ dw)
{
    int idx = blockIdx.x * blockDim.x + threadIdx.x;   // MM*AA
    int c = idx & (AA - 1);
    int m = idx >> 9;
    int b = m >> 11, s = m & (SS - 1);
    float acc = 0.f;
    #pragma unroll
    for (int k = 0; k < KW; k++) {
        int s2 = s + k - KW / 2;
        if (s2 >= 0 && s2 < SS)
            acc = fmaf(hid[(size_t)(b * SS + s2) * HIDD + AA + c], dw[c * KW + k], acc);
    }
    g_dw[idx] = acc;
}

// ---------------- softmax over K=9 within each (m,h) group of ckl ----------------
__global__ void softmax_kernel()
{
    int idx = blockIdx.x * blockDim.x + threadIdx.x;   // MM*NH
    float* p = g_ckl + (size_t)(idx >> 3) * (NH * KW) + (idx & 7) * KW;
    float mx = -INFINITY;
    float buf[KW];
    #pragma unroll
    for (int i = 0; i < KW; i++) { buf[i] = p[i]; mx = fmaxf(mx, buf[i]); }
    float sum = 0.f;
    #pragma unroll
    for (int i = 0; i < KW; i++) { buf[i] = __expf(buf[i] - mx); sum += buf[i]; }
    float inv = 1.f / sum;
    #pragma unroll
    for (int i = 0; i < KW; i++) p[i] = buf[i] * inv;
}

// ---------------- conv_out: windowed gather of col weighted by ckl -> out[..., 512:] ----
__global__ void convout_kernel(float* __restrict__ out)
{
    int idx = blockIdx.x * blockDim.x + threadIdx.x;   // MM*AA
    int c = idx & (AA - 1);
    int m = idx >> 9;
    int b = m >> 11, s = m & (SS - 1);
    int h = c >> 6;
    const float* ck = g_ckl + (size_t)m * (NH * KW) + h * KW;
    float acc = 0.f;
    #pragma unroll
    for (int k = 0; k < KW; k++) {
        int s2 = s + k - KW / 2;
        if (s2 >= 0 && s2 < SS)
            acc = fmaf(g_col[(size_t)(b * SS + s2) * AA + c], ck[k], acc);
    }
    out[(size_t)m * HIDD + AA + c] = acc;
}

// ---------------- flash attention fp32: Br=Bc=64, D=64, online softmax -------------
// grid (S/64, B*H), 256 threads, 4x4 microtiles for both QK^T and PV.
__global__ void attn_kernel(float* __restrict__ out)
{
    extern __shared__ float sm[];
    float* Qt = sm;                // [64][68], Qt[d*68+row]  (scaled)
    float* Kt = sm + 64 * 68;      // [64][68], Kt[d*68+col]
    float* Vs = sm + 2 * 64 * 68;  // [64][68], Vs[key*68+d]
    float* Pt = sm + 3 * 64 * 68;  // [64][68], Pt[key*68+row]

    const int tid = threadIdx.x;
    const int ty = tid >> 4, tx = tid & 15;
    const int q0 = blockIdx.x * 64;
    const int bh = blockIdx.y;
    const int h = bh & (NH - 1), b = bh >> 3;

    const float* Qg = g_q + (size_t)(b * SS) * AA + h * HD;
    const float* Kg = g_k + (size_t)(b * SS) * AA + h * HD;
    const float* Vg = g_v + (size_t)(b * SS) * AA + h * HD;

    #pragma unroll
    for (int i = 0; i < 16; i++) {
        int idx = tid + i * 256;
        int row = idx >> 6, d = idx & 63;
        Qt[d * 68 + row] = Qg[(size_t)(q0 + row) * AA + d] * 0.125f;
    }

    float o[4][4] = {};
    float mr[4], lr[4];
    #pragma unroll
    for (int r = 0; r < 4; r++) { mr[r] = -INFINITY; lr[r] = 0.f; }

    for (int kt = 0; kt < SS / 64; kt++) {
        __syncthreads();   // prior PV done reading Vs/Pt; Qt ready on first iter
        #pragma unroll
        for (int i = 0; i < 16; i++) {
            int idx = tid + i * 256;
            int key = idx >> 6, d = idx & 63;
            float kv = Kg[(size_t)(kt * 64 + key) * AA + d];
            float vv = Vg[(size_t)(kt * 64 + key) * AA + d];
            Kt[d * 68 + key] = kv;
            Vs[key * 68 + d] = vv;
        }
        __syncthreads();

        // S = Q K^T (scaled)
        float s[4][4] = {};
        #pragma unroll
        for (int d = 0; d < 64; d++) {
            float4 a4 = *(const float4*)&Qt[d * 68 + ty * 4];
            float4 b4 = *(const float4*)&Kt[d * 68 + tx * 4];
            float a[4] = {a4.x, a4.y, a4.z, a4.w};
            float bv[4] = {b4.x, b4.y, b4.z, b4.w};
            #pragma unroll
            for (int r = 0; r < 4; r++)
                #pragma unroll
                for (int c = 0; c < 4; c++)
                    s[r][c] = fmaf(a[r], bv[c], s[r][c]);
        }

        // online softmax per row (rows owned by the 16 lanes sharing ty)
        #pragma unroll
        for (int r = 0; r < 4; r++) {
            float tm = fmaxf(fmaxf(s[r][0], s[r][1]), fmaxf(s[r][2], s[r][3]));
            #pragma unroll
            for (int off = 8; off; off >>= 1)
                tm = fmaxf(tm, __shfl_xor_sync(0xffffffffu, tm, off));
            float mnew = fmaxf(mr[r], tm);
            float alpha = __expf(mr[r] - mnew);
            float ssum = 0.f;
            #pragma unroll
            for (int c = 0; c < 4; c++) {
                float p = __expf(s[r][c] - mnew);
                s[r][c] = p;
                ssum += p;
            }
            #pragma unroll
            for (int off = 8; off; off >>= 1)
                ssum += __shfl_xor_sync(0xffffffffu, ssum, off);
            lr[r] = lr[r] * alpha + ssum;
            mr[r] = mnew;
            #pragma unroll
            for (int c = 0; c < 4; c++) o[r][c] *= alpha;
        }

        // store P transposed: Pt[col][row]
        #pragma unroll
        for (int c = 0; c < 4; c++) {
            float4 pv = make_float4(s[0][c], s[1][c], s[2][c], s[3][c]);
            *(float4*)&Pt[(tx * 4 + c) * 68 + ty * 4] = pv;
        }
        __syncthreads();

        // O += P @ V
        #pragma unroll
        for (int key = 0; key < 64; key++) {
            float4 a4 = *(const float4*)&Pt[key * 68 + ty * 4];
            float4 b4 = *(const float4*)&Vs[key * 68 + tx * 4];
            float a[4] = {a4.x, a4.y, a4.z, a4.w};
            float bv[4] = {b4.x, b4.y, b4.z, b4.w};
            #pragma unroll
            for (int r = 0; r < 4; r++)
                #pragma unroll
                for (int c = 0; c < 4; c++)
                    o[r][c] = fmaf(a[r], bv[c], o[r][c]);
        }
    }

    #pragma unroll
    for (int r = 0; r < 4; r++) {
        float inv = 1.f / lr[r];
        float4 v4 = make_float4(o[r][0] * inv, o[r][1] * inv, o[r][2] * inv, o[r][3] * inv);
        *(float4*)&out[(size_t)(b * SS + q0 + ty * 4 + r) * HIDD + h * HD + tx * 4] = v4;
    }
}

// ---------------- launch ----------------
extern "C" void kernel_launch(void* const* d_in, const int* in_sizes, int n_in,
                              void* d_out, int out_size)
{
    const float* hid  = (const float*)d_in[0];
    const float* Wq   = (const float*)d_in[1];
    const float* bq   = (const float*)d_in[2];
    const float* Wk   = (const float*)d_in[3];
    const float* bk   = (const float*)d_in[4];
    const float* Wv   = (const float*)d_in[5];
    const float* bv   = (const float*)d_in[6];
    const float* dww  = (const float*)d_in[7];
    const float* pww  = (const float*)d_in[8];
    const float* sepb = (const float*)d_in[9];
    const float* Wck  = (const float*)d_in[10];
    const float* bck  = (const float*)d_in[11];
    const float* Wco  = (const float*)d_in[12];
    const float* bco  = (const float*)d_in[13];
    float* out = (float*)d_out;

    float *qp, *kp, *vp, *colp, *dwp, *cap, *cklp;
    cudaGetSymbolAddress((void**)&qp,   g_q);
    cudaGetSymbolAddress((void**)&kp,   g_k);
    cudaGetSymbolAddress((void**)&vp,   g_v);
    cudaGetSymbolAddress((void**)&colp, g_col);
    cudaGetSymbolAddress((void**)&dwp,  g_dw);
    cudaGetSymbolAddress((void**)&cap,  g_ca);
    cudaGetSymbolAddress((void**)&cklp, g_ckl);

    cudaFuncSetAttribute(attn_kernel, cudaFuncAttributeMaxDynamicSharedMemorySize, 4 * 64 * 68 * 4);

    dim3 g512(8, MM / 64), t256(256);

    // q, k, v from attention half; col from conv half
    gemm_kernel<<<g512, t256>>>(hid,        HIDD, Wq,  AA, bq,  nullptr, 0, qp,   AA);
    gemm_kernel<<<g512, t256>>>(hid,        HIDD, Wk,  AA, bk,  nullptr, 0, kp,   AA);
    gemm_kernel<<<g512, t256>>>(hid,        HIDD, Wv,  AA, bv,  nullptr, 0, vp,   AA);
    gemm_kernel<<<g512, t256>>>(hid + AA,   HIDD, Wco, AA, bco, nullptr, 0, colp, AA);

    // depthwise conv
    dwconv_kernel<<<MM * AA / 256, t256>>>(hid, dww);

    // pointwise conv + sep_b, fused elementwise * hs_conv  -> conv_attn
    gemm_kernel<<<g512, t256>>>(dwp, AA, pww, AA, sepb, hid + AA, HIDD, cap, AA);

    // ckl = conv_attn @ Wck^T + bck  (N=72)
    gemm_kernel<<<dim3(2, MM / 64), t256>>>(cap, AA, Wck, NH * KW, bck, nullptr, 0, cklp, NH * KW);

    // softmax over K=9
    softmax_kernel<<<MM * NH / 256, t256>>>();

    // conv output half
    convout_kernel<<<MM * AA / 256, t256>>>(out);

    // attention half
    attn_kernel<<<dim3(SS / 64, BB * NH), t256, 4 * 64 * 68 * 4>>>(out);
}

// round 3
// speedup vs baseline: 1.6351x; 1.6351x over previous
#include <cuda_runtime.h>
#include <math.h>

#define NH   8
#define HD   64
#define KW   9
#define AA   512
#define HIDD 1024
#define BB   4
#define SS   2048
#define MM   (BB*SS)   // 8192

// ---------------- scratch (device globals; no allocation) ----------------
__device__ float g_q[MM*AA];
__device__ float g_k[MM*AA];
__device__ float g_v[MM*AA];
__device__ float g_col[MM*AA];
__device__ float g_dw[MM*AA];
__device__ float g_ca[MM*AA];
__device__ float g_ckl[MM*NH*KW];

// ---------------- packed f32x2 FMA (sm_103a FFMA2 — 2x scalar FFMA rate) ----------
union F2U { float2 f; unsigned long long u; };

__device__ __forceinline__ float2 ffma2(float2 a, float2 b, float2 c) {
    F2U A, B, C, D; A.f = a; B.f = b; C.f = c;
    asm("fma.rn.f32x2 %0, %1, %2, %3;" : "=l"(D.u) : "l"(A.u), "l"(B.u), "l"(C.u));
    return D.f;
}

// ---------------- SGEMM: C[M,N] = X[M,512] @ W[N,512]^T + bias (opt *mul) ----------
// 128x128 tile, BK=16, 256 threads, 8x8 microtile, FFMA2, reg-staged prefetch.
__global__ __launch_bounds__(256, 2)
void gemm_kernel(const float* __restrict__ X, int ldx,
                 const float* __restrict__ W, int N,
                 const float* __restrict__ bias,
                 const float* __restrict__ mul, int ldmul,
                 float* __restrict__ C, int ldc)
{
    __shared__ __align__(16) float As[16][132];
    __shared__ __align__(16) float Bs[16][132];
    const int tid = threadIdx.x;
    const int ty = tid >> 4, tx = tid & 15;
    const int bm = blockIdx.y * 128, bn = blockIdx.x * 128;
    const int lr = tid >> 2;            // 0..63
    const int lc = (tid & 3) << 2;      // 0,4,8,12

    const float* Xp0 = X + (size_t)(bm + lr) * ldx + lc;
    const float* Xp1 = Xp0 + (size_t)64 * ldx;
    const int n0r = bn + lr, n1r = bn + lr + 64;
    const bool w0ok = n0r < N, w1ok = n1r < N;
    const float* Wp0 = W + (size_t)n0r * 512 + lc;
    const float* Wp1 = W + (size_t)n1r * 512 + lc;

    float4 xa0 = *(const float4*)Xp0;
    float4 xa1 = *(const float4*)Xp1;
    float4 wb0 = w0ok ? *(const float4*)Wp0 : make_float4(0.f,0.f,0.f,0.f);
    float4 wb1 = w1ok ? *(const float4*)Wp1 : make_float4(0.f,0.f,0.f,0.f);

    float2 acc[8][4];
    #pragma unroll
    for (int r = 0; r < 8; r++)
        #pragma unroll
        for (int c = 0; c < 4; c++) acc[r][c] = make_float2(0.f, 0.f);

    for (int k0 = 0; k0 < 512; k0 += 16) {
        As[lc+0][lr] = xa0.x; As[lc+1][lr] = xa0.y; As[lc+2][lr] = xa0.z; As[lc+3][lr] = xa0.w;
        As[lc+0][lr+64] = xa1.x; As[lc+1][lr+64] = xa1.y; As[lc+2][lr+64] = xa1.z; As[lc+3][lr+64] = xa1.w;
        Bs[lc+0][lr] = wb0.x; Bs[lc+1][lr] = wb0.y; Bs[lc+2][lr] = wb0.z; Bs[lc+3][lr] = wb0.w;
        Bs[lc+0][lr+64] = wb1.x; Bs[lc+1][lr+64] = wb1.y; Bs[lc+2][lr+64] = wb1.z; Bs[lc+3][lr+64] = wb1.w;
        __syncthreads();

        if (k0 + 16 < 512) {
            xa0 = *(const float4*)(Xp0 + k0 + 16);
            xa1 = *(const float4*)(Xp1 + k0 + 16);
            wb0 = w0ok ? *(const float4*)(Wp0 + k0 + 16) : make_float4(0.f,0.f,0.f,0.f);
            wb1 = w1ok ? *(const float4*)(Wp1 + k0 + 16) : make_float4(0.f,0.f,0.f,0.f);
        }

        #pragma unroll
        for (int k = 0; k < 16; k++) {
            float4 a0 = *(const float4*)&As[k][ty*8];
            float4 a1 = *(const float4*)&As[k][ty*8+4];
            float4 b0 = *(const float4*)&Bs[k][tx*8];
            float4 b1 = *(const float4*)&Bs[k][tx*8+4];
            float ar[8] = {a0.x,a0.y,a0.z,a0.w,a1.x,a1.y,a1.z,a1.w};
            float2 bp[4] = {make_float2(b0.x,b0.y), make_float2(b0.z,b0.w),
                            make_float2(b1.x,b1.y), make_float2(b1.z,b1.w)};
            #pragma unroll
            for (int r = 0; r < 8; r++) {
                float2 ap = make_float2(ar[r], ar[r]);
                #pragma unroll
                for (int c = 0; c < 4; c++)
                    acc[r][c] = ffma2(ap, bp[c], acc[r][c]);
            }
        }
        __syncthreads();
    }

    const float* accf = (const float*)acc;
    #pragma unroll
    for (int r = 0; r < 8; r++) {
        int m = bm + ty*8 + r;
        float* crow = C + (size_t)m * ldc;
        const float* mrow = mul ? (mul + (size_t)m * ldmul) : (const float*)0;
        #pragma unroll
        for (int c = 0; c < 8; c++) {
            int n = bn + tx*8 + c;
            if (n < N) {
                float v = accf[r*8 + c] + bias[n];
                if (mrow) v *= mrow[n];
                crow[n] = v;
            }
        }
    }
}

// ---------------- depthwise conv along seq (K=9, pad 4) ----------------
__global__ void dwconv_kernel(const float* __restrict__ hid, const float* __restrict__ dw)
{
    int idx = blockIdx.x * blockDim.x + threadIdx.x;   // MM*AA
    int c = idx & (AA - 1);
    int m = idx >> 9;
    int b = m >> 11, s = m & (SS - 1);
    float acc = 0.f;
    #pragma unroll
    for (int k = 0; k < KW; k++) {
        int s2 = s + k - KW / 2;
        if (s2 >= 0 && s2 < SS)
            acc = fmaf(hid[(size_t)(b * SS + s2) * HIDD + AA + c], dw[c * KW + k], acc);
    }
    g_dw[idx] = acc;
}

// ---------------- softmax over K=9 ----------------
__global__ void softmax_kernel()
{
    int idx = blockIdx.x * blockDim.x + threadIdx.x;   // MM*NH
    float* p = g_ckl + (size_t)(idx >> 3) * (NH * KW) + (idx & 7) * KW;
    float mx = -INFINITY;
    float buf[KW];
    #pragma unroll
    for (int i = 0; i < KW; i++) { buf[i] = p[i]; mx = fmaxf(mx, buf[i]); }
    float sum = 0.f;
    #pragma unroll
    for (int i = 0; i < KW; i++) { buf[i] = __expf(buf[i] - mx); sum += buf[i]; }
    float inv = 1.f / sum;
    #pragma unroll
    for (int i = 0; i < KW; i++) p[i] = buf[i] * inv;
}

// ---------------- conv_out ----------------
__global__ void convout_kernel(float* __restrict__ out)
{
    int idx = blockIdx.x * blockDim.x + threadIdx.x;   // MM*AA
    int c = idx & (AA - 1);
    int m = idx >> 9;
    int b = m >> 11, s = m & (SS - 1);
    int h = c >> 6;
    const float* ck = g_ckl + (size_t)m * (NH * KW) + h * KW;
    float acc = 0.f;
    #pragma unroll
    for (int k = 0; k < KW; k++) {
        int s2 = s + k - KW / 2;
        if (s2 >= 0 && s2 < SS)
            acc = fmaf(g_col[(size_t)(b * SS + s2) * AA + c], ck[k], acc);
    }
    out[(size_t)m * HIDD + AA + c] = acc;
}

// ---------------- flash attention fp32 FFMA2: Br=Bc=128, 256 threads ----------------
// QK^T: 8x8 microtile (128x128 S tile). PV + epilogue: 8x4 microtile (128x64 out).
__global__ __launch_bounds__(256, 1)
void attn_kernel(float* __restrict__ out)
{
    extern __shared__ __align__(16) float sm[];
    float* Qt = sm;                    // [64][132]  Qt[d*132+row], scaled
    float* Kt = Qt + 64*132;           // [64][132]  Kt[d*132+key]
    float* Vs = Kt + 64*132;           // [128][68]  Vs[key*68+d]
    float* Pt = Vs + 128*68;           // [128][132] Pt[row*132+key]

    const int tid = threadIdx.x;
    const int ty = tid >> 4, tx = tid & 15;
    const int q0 = blockIdx.x * 128;
    const int h = blockIdx.y & (NH - 1), b = blockIdx.y >> 3;

    const float* Qg = g_q + (size_t)(b * SS) * AA + h * HD;
    const float* Kg = g_k + (size_t)(b * SS) * AA + h * HD;
    const float* Vg = g_v + (size_t)(b * SS) * AA + h * HD;

    // load Q (128x64), transposed + scaled
    #pragma unroll
    for (int i = 0; i < 8; i++) {
        int flat = tid + i * 256;          // float4 index, 0..2047
        int row = flat >> 4;
        int c4 = (flat & 15) << 2;
        float4 qv = *(const float4*)(Qg + (size_t)(q0 + row) * AA + c4);
        Qt[(c4+0)*132 + row] = qv.x * 0.125f;
        Qt[(c4+1)*132 + row] = qv.y * 0.125f;
        Qt[(c4+2)*132 + row] = qv.z * 0.125f;
        Qt[(c4+3)*132 + row] = qv.w * 0.125f;
    }

    float2 o[8][2];                     // rows ty*8+r, cols tx*4 .. tx*4+3
    float mr[8], lr_[8];
    #pragma unroll
    for (int r = 0; r < 8; r++) {
        mr[r] = -INFINITY; lr_[r] = 0.f;
        o[r][0] = make_float2(0.f, 0.f);
        o[r][1] = make_float2(0.f, 0.f);
    }

    for (int kt = 0; kt < SS / 128; kt++) {
        __syncthreads();   // previous PV done with Vs/Pt; Q load done (first iter)
        #pragma unroll
        for (int i = 0; i < 8; i++) {
            int flat = tid + i * 256;
            int row = flat >> 4;
            int c4 = (flat & 15) << 2;
            size_t gidx = (size_t)(kt * 128 + row) * AA + c4;
            float4 kv = *(const float4*)(Kg + gidx);
            float4 vv = *(const float4*)(Vg + gidx);
            Kt[(c4+0)*132 + row] = kv.x;
            Kt[(c4+1)*132 + row] = kv.y;
            Kt[(c4+2)*132 + row] = kv.z;
            Kt[(c4+3)*132 + row] = kv.w;
            *(float4*)&Vs[row * 68 + c4] = vv;
        }
        __syncthreads();

        // S = Q K^T (scaled): 8x8 microtile over 128x128 tile
        float2 s2[8][4];
        #pragma unroll
        for (int r = 0; r < 8; r++)
            #pragma unroll
            for (int c = 0; c < 4; c++) s2[r][c] = make_float2(0.f, 0.f);

        #pragma unroll 8
        for (int d = 0; d < 64; d++) {
            float4 a0 = *(const float4*)&Qt[d*132 + ty*8];
            float4 a1 = *(const float4*)&Qt[d*132 + ty*8 + 4];
            float4 b0 = *(const float4*)&Kt[d*132 + tx*8];
            float4 b1 = *(const float4*)&Kt[d*132 + tx*8 + 4];
            float ar[8] = {a0.x,a0.y,a0.z,a0.w,a1.x,a1.y,a1.z,a1.w};
            float2 bp[4] = {make_float2(b0.x,b0.y), make_float2(b0.z,b0.w),
                            make_float2(b1.x,b1.y), make_float2(b1.z,b1.w)};
            #pragma unroll
            for (int r = 0; r < 8; r++) {
                float2 ap = make_float2(ar[r], ar[r]);
                #pragma unroll
                for (int c = 0; c < 4; c++)
                    s2[r][c] = ffma2(ap, bp[c], s2[r][c]);
            }
        }

        // online softmax per row (16 lanes with same ty share a row)
        float* sp = (float*)s2;    // sp[r*8 + c]
        #pragma unroll
        for (int r = 0; r < 8; r++) {
            float tm = sp[r*8];
            #pragma unroll
            for (int c = 1; c < 8; c++) tm = fmaxf(tm, sp[r*8+c]);
            #pragma unroll
            for (int off = 8; off; off >>= 1)
                tm = fmaxf(tm, __shfl_xor_sync(0xffffffffu, tm, off));
            float mnew = fmaxf(mr[r], tm);
            float alpha = __expf(mr[r] - mnew);
            float ssum = 0.f;
            #pragma unroll
            for (int c = 0; c < 8; c++) {
                float e = __expf(sp[r*8+c] - mnew);
                sp[r*8+c] = e;
                ssum += e;
            }
            #pragma unroll
            for (int off = 8; off; off >>= 1)
                ssum += __shfl_xor_sync(0xffffffffu, ssum, off);
            lr_[r] = lr_[r] * alpha + ssum;
            mr[r] = mnew;
            o[r][0].x *= alpha; o[r][0].y *= alpha;
            o[r][1].x *= alpha; o[r][1].y *= alpha;
        }

        // stage P: Pt[row][key]
        #pragma unroll
        for (int r = 0; r < 8; r++) {
            *(float4*)&Pt[(ty*8+r)*132 + tx*8]     = make_float4(sp[r*8+0], sp[r*8+1], sp[r*8+2], sp[r*8+3]);
            *(float4*)&Pt[(ty*8+r)*132 + tx*8 + 4] = make_float4(sp[r*8+4], sp[r*8+5], sp[r*8+6], sp[r*8+7]);
        }
        __syncthreads();

        // O += P @ V : 8x4 microtile over 128x64 output
        #pragma unroll 4
        for (int key = 0; key < 128; key++) {
            float4 b0 = *(const float4*)&Vs[key*68 + tx*4];
            float2 bp0 = make_float2(b0.x, b0.y);
            float2 bp1 = make_float2(b0.z, b0.w);
            #pragma unroll
            for (int r = 0; r < 8; r++) {
                float p = Pt[(ty*8+r)*132 + key];
                float2 ap = make_float2(p, p);
                o[r][0] = ffma2(ap, bp0, o[r][0]);
                o[r][1] = ffma2(ap, bp1, o[r][1]);
            }
        }
    }

    // epilogue: rows ty*8+r, cols h*HD + tx*4 .. +3
    float* Og = out + (size_t)(b * SS + q0 + ty*8) * HIDD + h * HD + tx*4;
    #pragma unroll
    for (int r = 0; r < 8; r++) {
        float inv = 1.f / lr_[r];
        float4 v4 = make_float4(o[r][0].x*inv, o[r][0].y*inv, o[r][1].x*inv, o[r][1].y*inv);
        *(float4*)(Og + (size_t)r * HIDD) = v4;
    }
}

// ---------------- launch ----------------
extern "C" void kernel_launch(void* const* d_in, const int* in_sizes, int n_in,
                              void* d_out, int out_size)
{
    const float* hid  = (const float*)d_in[0];
    const float* Wq   = (const float*)d_in[1];
    const float* bq   = (const float*)d_in[2];
    const float* Wk   = (const float*)d_in[3];
    const float* bk   = (const float*)d_in[4];
    const float* Wv   = (const float*)d_in[5];
    const float* bv   = (const float*)d_in[6];
    const float* dww  = (const float*)d_in[7];
    const float* pww  = (const float*)d_in[8];
    const float* sepb = (const float*)d_in[9];
    const float* Wck  = (const float*)d_in[10];
    const float* bck  = (const float*)d_in[11];
    const float* Wco  = (const float*)d_in[12];
    const float* bco  = (const float*)d_in[13];
    float* out = (float*)d_out;

    float *qp, *kp, *vp, *colp, *dwp, *cap, *cklp;
    cudaGetSymbolAddress((void**)&qp,   g_q);
    cudaGetSymbolAddress((void**)&kp,   g_k);
    cudaGetSymbolAddress((void**)&vp,   g_v);
    cudaGetSymbolAddress((void**)&colp, g_col);
    cudaGetSymbolAddress((void**)&dwp,  g_dw);
    cudaGetSymbolAddress((void**)&cap,  g_ca);
    cudaGetSymbolAddress((void**)&cklp, g_ckl);

    const int ATTN_SMEM = (64*132*2 + 128*68 + 128*132) * 4;   // 169984 B
    cudaFuncSetAttribute(attn_kernel, cudaFuncAttributeMaxDynamicSharedMemorySize, ATTN_SMEM);

    dim3 g512(4, MM / 128), t256(256);

    gemm_kernel<<<g512, t256>>>(hid,      HIDD, Wq,  AA, bq,  nullptr, 0, qp,   AA);
    gemm_kernel<<<g512, t256>>>(hid,      HIDD, Wk,  AA, bk,  nullptr, 0, kp,   AA);
    gemm_kernel<<<g512, t256>>>(hid,      HIDD, Wv,  AA, bv,  nullptr, 0, vp,   AA);
    gemm_kernel<<<g512, t256>>>(hid + AA, HIDD, Wco, AA, bco, nullptr, 0, colp, AA);

    dwconv_kernel<<<MM * AA / 256, t256>>>(hid, dww);

    // pointwise conv + sep_b, fused elementwise * hs_conv -> conv_attn
    gemm_kernel<<<g512, t256>>>(dwp, AA, pww, AA, sepb, hid + AA, HIDD, cap, AA);

    // ckl = conv_attn @ Wck^T + bck  (N=72)
    gemm_kernel<<<dim3(1, MM / 128), t256>>>(cap, AA, Wck, NH * KW, bck, nullptr, 0, cklp, NH * KW);

    softmax_kernel<<<MM * NH / 256, t256>>>();
    convout_kernel<<<MM * AA / 256, t256>>>(out);

    attn_kernel<<<dim3(SS / 128, BB * NH), t256, ATTN_SMEM>>>(out);
}

// round 4
// speedup vs baseline: 3.4989x; 2.1398x over previous
#include <cuda_runtime.h>
#include <math.h>
#include <stdint.h>

#define NH   8
#define HD   64
#define KW   9
#define AA   512
#define HIDD 1024
#define BB   4
#define SS   2048
#define MM   (BB*SS)   // 8192

// ---------------- scratch (device globals; no allocation) ----------------
__device__ float g_q[MM*AA];
__device__ float g_k[MM*AA];
__device__ float g_v[MM*AA];
__device__ float g_col[MM*AA];
__device__ float g_dw[MM*AA];
__device__ float g_ca[MM*AA];
__device__ float g_ckl[MM*NH*KW];

// ---------------- helpers ----------------
__device__ __forceinline__ float to_tf32(float x) {
    asm("cvt.rna.tf32.f32 %0, %1;" : "=f"(x) : "f"(x));
    return x;
}

__device__ __forceinline__ void mma_tf32(float c[4],
    uint32_t a0, uint32_t a1, uint32_t a2, uint32_t a3,
    uint32_t b0, uint32_t b1)
{
    asm volatile("mma.sync.aligned.m16n8k8.row.col.f32.tf32.tf32.f32 "
        "{%0,%1,%2,%3}, {%4,%5,%6,%7}, {%8,%9}, {%0,%1,%2,%3};"
        : "+f"(c[0]), "+f"(c[1]), "+f"(c[2]), "+f"(c[3])
        : "r"(a0), "r"(a1), "r"(a2), "r"(a3), "r"(b0), "r"(b1));
}

// fast exp on FMA pipe (avoids MUFU bottleneck). x <= 0 expected; handles -inf.
__device__ __forceinline__ float fast_exp(float x) {
    float t = fmaxf(x * 1.4426950408889634f, -126.0f);
    float z = t + 12582912.0f;                      // round-to-nearest-int magic
    int   n = __float_as_int(z) - 0x4B400000;
    float r = t - (z - 12582912.0f);                // r in [-0.5, 0.5]
    float p = fmaf(r, 0.009618129f, 0.055504109f);
    p = fmaf(r, p, 0.240226507f);
    p = fmaf(r, p, 0.693147181f);
    p = fmaf(r, p, 1.0f);
    return __int_as_float(__float_as_int(p) + (n << 23));
}

#define SBITS(arr, idx) (*(const uint32_t*)&(arr)[idx])

// ---------------- tf32 tensor-core SGEMM: C[M,N] = X @ W^T + bias (opt *mul) --------
// 128x128 tile, BK=32, 256 threads (8 warps as 4x2), warp tile 32x64, m16n8k8.
__global__ __launch_bounds__(256)
void gemm_kernel(const float* __restrict__ X, int ldx,
                 const float* __restrict__ W, int N,
                 const float* __restrict__ bias,
                 const float* __restrict__ mul, int ldmul,
                 float* __restrict__ C, int ldc)
{
    __shared__ __align__(16) float Xs[128 * 36];   // stride 36 (=4 mod 32)
    __shared__ __align__(16) float Ws[128 * 36];

    const int tid  = threadIdx.x;
    const int lane = tid & 31, wid = tid >> 5;
    const int wm = (wid >> 1) * 32, wn = (wid & 1) * 64;
    const int bm = blockIdx.y * 128, bn = blockIdx.x * 128;
    const int lq = lane >> 2;     // l/4
    const int lr = lane & 3;      // l%4

    float4 xf[4], wf[4];
    int rowi[4], kqi[4];
    #pragma unroll
    for (int i = 0; i < 4; i++) {
        int fl = tid + i * 256;
        rowi[i] = fl >> 3;
        kqi[i]  = (fl & 7) << 2;
        xf[i] = *(const float4*)(X + (size_t)(bm + rowi[i]) * ldx + kqi[i]);
        int n = bn + rowi[i];
        wf[i] = (n < N) ? *(const float4*)(W + (size_t)n * 512 + kqi[i])
                        : make_float4(0.f, 0.f, 0.f, 0.f);
    }

    float c[2][8][4];
    #pragma unroll
    for (int mt = 0; mt < 2; mt++)
        #pragma unroll
        for (int nt = 0; nt < 8; nt++)
            #pragma unroll
            for (int j = 0; j < 4; j++) c[mt][nt][j] = 0.f;

    for (int k0 = 0; k0 < 512; k0 += 32) {
        #pragma unroll
        for (int i = 0; i < 4; i++) {
            *(float4*)&Xs[rowi[i] * 36 + kqi[i]] =
                make_float4(to_tf32(xf[i].x), to_tf32(xf[i].y), to_tf32(xf[i].z), to_tf32(xf[i].w));
            *(float4*)&Ws[rowi[i] * 36 + kqi[i]] =
                make_float4(to_tf32(wf[i].x), to_tf32(wf[i].y), to_tf32(wf[i].z), to_tf32(wf[i].w));
        }
        __syncthreads();

        if (k0 + 32 < 512) {
            #pragma unroll
            for (int i = 0; i < 4; i++) {
                xf[i] = *(const float4*)(X + (size_t)(bm + rowi[i]) * ldx + k0 + 32 + kqi[i]);
                int n = bn + rowi[i];
                wf[i] = (n < N) ? *(const float4*)(W + (size_t)n * 512 + k0 + 32 + kqi[i])
                                : make_float4(0.f, 0.f, 0.f, 0.f);
            }
        }

        #pragma unroll
        for (int ks = 0; ks < 4; ks++) {
            const int kk = ks * 8;
            uint32_t a[2][4], b[8][2];
            #pragma unroll
            for (int mt = 0; mt < 2; mt++) {
                int base = (wm + 16 * mt + lq) * 36 + kk + lr;
                a[mt][0] = SBITS(Xs, base);
                a[mt][1] = SBITS(Xs, base + 8 * 36);
                a[mt][2] = SBITS(Xs, base + 4);
                a[mt][3] = SBITS(Xs, base + 8 * 36 + 4);
            }
            #pragma unroll
            for (int nt = 0; nt < 8; nt++) {
                int base = (wn + 8 * nt + lq) * 36 + kk + lr;
                b[nt][0] = SBITS(Ws, base);
                b[nt][1] = SBITS(Ws, base + 4);
            }
            #pragma unroll
            for (int mt = 0; mt < 2; mt++)
                #pragma unroll
                for (int nt = 0; nt < 8; nt++)
                    mma_tf32(c[mt][nt], a[mt][0], a[mt][1], a[mt][2], a[mt][3],
                             b[nt][0], b[nt][1]);
        }
        __syncthreads();
    }

    // epilogue: c0,c1 = row l/4, cols 2(l%4),+1 ; c2,c3 = row+8
    #pragma unroll
    for (int mt = 0; mt < 2; mt++)
        #pragma unroll
        for (int j = 0; j < 2; j++) {
            int row = bm + wm + 16 * mt + lq + 8 * j;
            float* crow = C + (size_t)row * ldc;
            const float* mrow = mul ? (mul + (size_t)row * ldmul) : (const float*)0;
            #pragma unroll
            for (int nt = 0; nt < 8; nt++) {
                int col = bn + wn + 8 * nt + 2 * lr;
                if (col < N) {
                    float v0 = c[mt][nt][2 * j]     + bias[col];
                    float v1 = c[mt][nt][2 * j + 1] + bias[col + 1];
                    if (mrow) { v0 *= mrow[col]; v1 *= mrow[col + 1]; }
                    *(float2*)(crow + col) = make_float2(v0, v1);
                }
            }
        }
}

// ---------------- depthwise conv along seq (K=9, pad 4) ----------------
__global__ void dwconv_kernel(const float* __restrict__ hid, const float* __restrict__ dw)
{
    int idx = blockIdx.x * blockDim.x + threadIdx.x;
    int c = idx & (AA - 1);
    int m = idx >> 9;
    int b = m >> 11, s = m & (SS - 1);
    float acc = 0.f;
    #pragma unroll
    for (int k = 0; k < KW; k++) {
        int s2 = s + k - KW / 2;
        if (s2 >= 0 && s2 < SS)
            acc = fmaf(hid[(size_t)(b * SS + s2) * HIDD + AA + c], dw[c * KW + k], acc);
    }
    g_dw[idx] = acc;
}

// ---------------- softmax over K=9 ----------------
__global__ void softmax_kernel()
{
    int idx = blockIdx.x * blockDim.x + threadIdx.x;
    float* p = g_ckl + (size_t)(idx >> 3) * (NH * KW) + (idx & 7) * KW;
    float mx = -INFINITY;
    float buf[KW];
    #pragma unroll
    for (int i = 0; i < KW; i++) { buf[i] = p[i]; mx = fmaxf(mx, buf[i]); }
    float sum = 0.f;
    #pragma unroll
    for (int i = 0; i < KW; i++) { buf[i] = fast_exp(buf[i] - mx); sum += buf[i]; }
    float inv = 1.f / sum;
    #pragma unroll
    for (int i = 0; i < KW; i++) p[i] = buf[i] * inv;
}

// ---------------- conv_out ----------------
__global__ void convout_kernel(float* __restrict__ out)
{
    int idx = blockIdx.x * blockDim.x + threadIdx.x;
    int c = idx & (AA - 1);
    int m = idx >> 9;
    int b = m >> 11, s = m & (SS - 1);
    int h = c >> 6;
    const float* ck = g_ckl + (size_t)m * (NH * KW) + h * KW;
    float acc = 0.f;
    #pragma unroll
    for (int k = 0; k < KW; k++) {
        int s2 = s + k - KW / 2;
        if (s2 >= 0 && s2 < SS)
            acc = fmaf(g_col[(size_t)(b * SS + s2) * AA + c], ck[k], acc);
    }
    out[(size_t)m * HIDD + AA + c] = acc;
}

// ---------------- flash attention: tf32 mma + fast_exp --------------------
// 128 q-rows/block, 8 warps; warp w owns q-rows 16w..16w+15 (QK, softmax, PV all
// warp-private in the row dim -> only __syncwarp between P store and PV).
__global__ __launch_bounds__(256)
void attn_kernel(float* __restrict__ out)
{
    extern __shared__ __align__(16) float sm[];
    float* Qs = sm;                  // [128][68]  (stride 68 = 4 mod 32)
    float* Ks = Qs + 128 * 68;       // [128][72]  (stride 72 = 8 mod 32)
    float* Vs = Ks + 128 * 72;       // [128][72]
    float* Pt = Vs + 128 * 72;       // [128][132] (stride 132 = 4 mod 32)

    const int tid  = threadIdx.x;
    const int lane = tid & 31, wid = tid >> 5;
    const int lq = lane >> 2, lr = lane & 3;
    const int q0 = blockIdx.x * 128;
    const int h = blockIdx.y & (NH - 1), b = blockIdx.y >> 3;

    const float* Qg = g_q + (size_t)(b * SS) * AA + h * HD;
    const float* Kg = g_k + (size_t)(b * SS) * AA + h * HD;
    const float* Vg = g_v + (size_t)(b * SS) * AA + h * HD;

    // load Q (128x64), scale + tf32
    #pragma unroll
    for (int i = 0; i < 8; i++) {
        int fl = tid + i * 256;
        int row = fl >> 4, c4 = (fl & 15) << 2;
        float4 qv = *(const float4*)(Qg + (size_t)(q0 + row) * AA + c4);
        *(float4*)&Qs[row * 68 + c4] = make_float4(
            to_tf32(qv.x * 0.125f), to_tf32(qv.y * 0.125f),
            to_tf32(qv.z * 0.125f), to_tf32(qv.w * 0.125f));
    }

    float o[8][4];
    #pragma unroll
    for (int nt = 0; nt < 8; nt++)
        #pragma unroll
        for (int j = 0; j < 4; j++) o[nt][j] = 0.f;
    float mr[2] = {-INFINITY, -INFINITY}, lr_[2] = {0.f, 0.f};

    const int arow = wid * 16 + lq;       // this thread's base q-row (local)

    for (int kt = 0; kt < 16; kt++) {
        __syncthreads();
        #pragma unroll
        for (int i = 0; i < 8; i++) {
            int fl = tid + i * 256;
            int row = fl >> 4, c4 = (fl & 15) << 2;
            size_t g = (size_t)(kt * 128 + row) * AA + c4;
            float4 kv = *(const float4*)(Kg + g);
            float4 vv = *(const float4*)(Vg + g);
            *(float4*)&Ks[row * 72 + c4] = make_float4(
                to_tf32(kv.x), to_tf32(kv.y), to_tf32(kv.z), to_tf32(kv.w));
            *(float4*)&Vs[row * 72 + c4] = make_float4(
                to_tf32(vv.x), to_tf32(vv.y), to_tf32(vv.z), to_tf32(vv.w));
        }
        __syncthreads();

        // S = Q K^T : per warp 16 rows x 128 keys (16 n-tiles), k = d (8 steps)
        float s[16][4];
        #pragma unroll
        for (int nt = 0; nt < 16; nt++)
            #pragma unroll
            for (int j = 0; j < 4; j++) s[nt][j] = 0.f;

        #pragma unroll
        for (int ks = 0; ks < 8; ks++) {
            const int kk = ks * 8;
            int abase = arow * 68 + kk + lr;
            uint32_t a0 = SBITS(Qs, abase);
            uint32_t a1 = SBITS(Qs, abase + 8 * 68);
            uint32_t a2 = SBITS(Qs, abase + 4);
            uint32_t a3 = SBITS(Qs, abase + 8 * 68 + 4);
            #pragma unroll
            for (int nt = 0; nt < 16; nt++) {
                int bbase = (8 * nt + lq) * 72 + kk + lr;
                mma_tf32(s[nt], a0, a1, a2, a3, SBITS(Ks, bbase), SBITS(Ks, bbase + 4));
            }
        }

        // online softmax: thread owns 2 rows (l/4, l/4+8); 4 lanes (lane%4) per row
        #pragma unroll
        for (int j = 0; j < 2; j++) {
            float tm = -INFINITY;
            #pragma unroll
            for (int nt = 0; nt < 16; nt++)
                tm = fmaxf(tm, fmaxf(s[nt][2*j], s[nt][2*j+1]));
            tm = fmaxf(tm, __shfl_xor_sync(0xffffffffu, tm, 1));
            tm = fmaxf(tm, __shfl_xor_sync(0xffffffffu, tm, 2));
            float mnew = fmaxf(mr[j], tm);
            float alpha = fast_exp(mr[j] - mnew);
            float sum = 0.f;
            #pragma unroll
            for (int nt = 0; nt < 16; nt++) {
                float e0 = fast_exp(s[nt][2*j]   - mnew);
                float e1 = fast_exp(s[nt][2*j+1] - mnew);
                sum += e0 + e1;
                s[nt][2*j]   = to_tf32(e0);
                s[nt][2*j+1] = to_tf32(e1);
            }
            sum += __shfl_xor_sync(0xffffffffu, sum, 1);
            sum += __shfl_xor_sync(0xffffffffu, sum, 2);
            lr_[j] = lr_[j] * alpha + sum;
            mr[j] = mnew;
            #pragma unroll
            for (int nt = 0; nt < 8; nt++) {
                o[nt][2*j]   *= alpha;
                o[nt][2*j+1] *= alpha;
            }
        }

        // stage P (warp-private rows)
        #pragma unroll
        for (int j = 0; j < 2; j++)
            #pragma unroll
            for (int nt = 0; nt < 16; nt++)
                *(float2*)&Pt[(arow + 8*j) * 132 + 8*nt + 2*lr] =
                    make_float2(s[nt][2*j], s[nt][2*j+1]);
        __syncwarp();

        // O += P @ V : per warp 16 rows x 64 d (8 n-tiles), k = key (16 steps)
        #pragma unroll
        for (int kk2 = 0; kk2 < 16; kk2++) {
            const int k0 = 8 * kk2;
            int abase = arow * 132 + k0 + lr;
            uint32_t a0 = SBITS(Pt, abase);
            uint32_t a1 = SBITS(Pt, abase + 8 * 132);
            uint32_t a2 = SBITS(Pt, abase + 4);
            uint32_t a3 = SBITS(Pt, abase + 8 * 132 + 4);
            #pragma unroll
            for (int nt = 0; nt < 8; nt++) {
                int bbase = (k0 + lr) * 72 + 8 * nt + lq;
                mma_tf32(o[nt], a0, a1, a2, a3, SBITS(Vs, bbase), SBITS(Vs, bbase + 4 * 72));
            }
        }
    }

    // epilogue
    #pragma unroll
    for (int j = 0; j < 2; j++) {
        float inv = 1.f / lr_[j];
        size_t row = (size_t)(b * SS + q0 + arow + 8 * j);
        #pragma unroll
        for (int nt = 0; nt < 8; nt++) {
            int col = h * HD + 8 * nt + 2 * lr;
            *(float2*)&out[row * HIDD + col] =
                make_float2(o[nt][2*j] * inv, o[nt][2*j+1] * inv);
        }
    }
}

// ---------------- launch ----------------
extern "C" void kernel_launch(void* const* d_in, const int* in_sizes, int n_in,
                              void* d_out, int out_size)
{
    const float* hid  = (const float*)d_in[0];
    const float* Wq   = (const float*)d_in[1];
    const float* bq   = (const float*)d_in[2];
    const float* Wk   = (const float*)d_in[3];
    const float* bk   = (const float*)d_in[4];
    const float* Wv   = (const float*)d_in[5];
    const float* bv   = (const float*)d_in[6];
    const float* dww  = (const float*)d_in[7];
    const float* pww  = (const float*)d_in[8];
    const float* sepb = (const float*)d_in[9];
    const float* Wck  = (const float*)d_in[10];
    const float* bck  = (const float*)d_in[11];
    const float* Wco  = (const float*)d_in[12];
    const float* bco  = (const float*)d_in[13];
    float* out = (float*)d_out;

    float *qp, *kp, *vp, *colp, *dwp, *cap, *cklp;
    cudaGetSymbolAddress((void**)&qp,   g_q);
    cudaGetSymbolAddress((void**)&kp,   g_k);
    cudaGetSymbolAddress((void**)&vp,   g_v);
    cudaGetSymbolAddress((void**)&colp, g_col);
    cudaGetSymbolAddress((void**)&dwp,  g_dw);
    cudaGetSymbolAddress((void**)&cap,  g_ca);
    cudaGetSymbolAddress((void**)&cklp, g_ckl);

    const int ATTN_SMEM = (128*68 + 128*72 + 128*72 + 128*132) * 4;   // 176128 B
    cudaFuncSetAttribute(attn_kernel, cudaFuncAttributeMaxDynamicSharedMemorySize, ATTN_SMEM);

    dim3 g512(4, MM / 128), t256(256);

    gemm_kernel<<<g512, t256>>>(hid,      HIDD, Wq,  AA, bq,  nullptr, 0, qp,   AA);
    gemm_kernel<<<g512, t256>>>(hid,      HIDD, Wk,  AA, bk,  nullptr, 0, kp,   AA);
    gemm_kernel<<<g512, t256>>>(hid,      HIDD, Wv,  AA, bv,  nullptr, 0, vp,   AA);
    gemm_kernel<<<g512, t256>>>(hid + AA, HIDD, Wco, AA, bco, nullptr, 0, colp, AA);

    dwconv_kernel<<<MM * AA / 256, t256>>>(hid, dww);

    // pointwise conv + sep_b, fused elementwise * hs_conv -> conv_attn
    gemm_kernel<<<g512, t256>>>(dwp, AA, pww, AA, sepb, hid + AA, HIDD, cap, AA);

    // ckl = conv_attn @ Wck^T + bck  (N=72)
    gemm_kernel<<<dim3(1, MM / 128), t256>>>(cap, AA, Wck, NH * KW, bck, nullptr, 0, cklp, NH * KW);

    softmax_kernel<<<MM * NH / 256, t256>>>();
    convout_kernel<<<MM * AA / 256, t256>>>(out);

    attn_kernel<<<dim3(SS / 128, BB * NH), t256, ATTN_SMEM>>>(out);
}

// round 5
// speedup vs baseline: 3.8508x; 1.1006x over previous
#include <cuda_runtime.h>
#include <math.h>
#include <stdint.h>

#define NH   8
#define HD   64
#define KW   9
#define AA   512
#define HIDD 1024
#define BB   4
#define SS   2048
#define MM   (BB*SS)   // 8192

// ---------------- scratch (device globals; no allocation) ----------------
__device__ float g_q[MM*AA];
__device__ float g_k[MM*AA];
__device__ float g_v[MM*AA];
__device__ float g_col[MM*AA];
__device__ float g_dw[MM*AA];
__device__ float g_ca[MM*AA];
__device__ float g_ckl[MM*NH*KW];
__device__ float g_hid[MM*HIDD];                    // tf32-rounded hidden_states
__device__ float g_wbuf[5*AA*AA + NH*KW*AA];        // tf32-rounded weights

// ---------------- helpers ----------------
__device__ __forceinline__ float to_tf32(float x) {
    asm("cvt.rna.tf32.f32 %0, %1;" : "=f"(x) : "f"(x));
    return x;
}

__device__ __forceinline__ void mma_tf32(float c[4],
    uint32_t a0, uint32_t a1, uint32_t a2, uint32_t a3,
    uint32_t b0, uint32_t b1)
{
    asm volatile("mma.sync.aligned.m16n8k8.row.col.f32.tf32.tf32.f32 "
        "{%0,%1,%2,%3}, {%4,%5,%6,%7}, {%8,%9}, {%0,%1,%2,%3};"
        : "+f"(c[0]), "+f"(c[1]), "+f"(c[2]), "+f"(c[3])
        : "r"(a0), "r"(a1), "r"(a2), "r"(a3), "r"(b0), "r"(b1));
}

// fast exp on FMA pipe (avoids MUFU bottleneck). x <= 0 expected; handles -inf.
__device__ __forceinline__ float fast_exp(float x) {
    float t = fmaxf(x * 1.4426950408889634f, -126.0f);
    float z = t + 12582912.0f;
    int   n = __float_as_int(z) - 0x4B400000;
    float r = t - (z - 12582912.0f);
    float p = fmaf(r, 0.009618129f, 0.055504109f);
    p = fmaf(r, p, 0.240226507f);
    p = fmaf(r, p, 0.693147181f);
    p = fmaf(r, p, 1.0f);
    return __int_as_float(__float_as_int(p) + (n << 23));
}

__device__ __forceinline__ void cp16(uint32_t saddr, const void* g, bool pred) {
    asm volatile("cp.async.ca.shared.global [%0], [%1], 16, %2;"
                 :: "r"(saddr), "l"(g), "r"(pred ? 16u : 0u));
}

#define SBITS(arr, idx) (*(const uint32_t*)&(arr)[idx])

// ---------------- tf32 pre-rounding pass ----------------
struct CSlot { const float* src; float* dst; int n4; };
struct CArgs { CSlot s[7]; };

__global__ void cvt_kernel(CArgs a)
{
    CSlot c = a.s[blockIdx.z];
    const float4* src = (const float4*)c.src;
    float4* dst = (float4*)c.dst;
    for (int i = blockIdx.x * blockDim.x + threadIdx.x; i < c.n4;
         i += gridDim.x * blockDim.x) {
        float4 v = src[i];
        dst[i] = make_float4(to_tf32(v.x), to_tf32(v.y), to_tf32(v.z), to_tf32(v.w));
    }
}

// ---------------- tf32 tensor-core GEMM, cp.async double-buffered ----------------
struct GSlot {
    const float* X; const float* W; const float* bias; const float* mul;
    float* C; int ldx; int ldmul; int ldc; int N; int rnd;
};
struct GArgs { GSlot s[4]; };

__global__ __launch_bounds__(256, 2)
void gemm_kernel(GArgs args)
{
    GSlot g = args.s[blockIdx.z];
    extern __shared__ __align__(16) float smg[];
    float* Xs = smg;                 // [2][128*36]
    float* Ws = smg + 2 * 4608;      // [2][128*36]

    const int tid  = threadIdx.x;
    const int lane = tid & 31, wid = tid >> 5;
    const int wm = (wid >> 1) * 32, wn = (wid & 1) * 64;
    const int bm = blockIdx.y * 128, bn = blockIdx.x * 128;
    const int lq = lane >> 2, lr = lane & 3;

    int rowi[4], kqi[4];
    #pragma unroll
    for (int i = 0; i < 4; i++) {
        int fl = tid + i * 256;
        rowi[i] = fl >> 3;
        kqi[i]  = (fl & 7) << 2;
    }
    const uint32_t xsa = (uint32_t)__cvta_generic_to_shared(Xs);
    const uint32_t wsa = (uint32_t)__cvta_generic_to_shared(Ws);

    float c[2][8][4];
    #pragma unroll
    for (int mt = 0; mt < 2; mt++)
        #pragma unroll
        for (int nt = 0; nt < 8; nt++)
            #pragma unroll
            for (int j = 0; j < 4; j++) c[mt][nt][j] = 0.f;

    // prologue: stage chunk 0 into buffer 0
    #pragma unroll
    for (int i = 0; i < 4; i++) {
        cp16(xsa + (rowi[i]*36 + kqi[i]) * 4,
             g.X + (size_t)(bm + rowi[i]) * g.ldx + kqi[i], true);
        int n = bn + rowi[i];
        int nc = n < g.N ? n : 0;
        cp16(wsa + (rowi[i]*36 + kqi[i]) * 4,
             g.W + (size_t)nc * 512 + kqi[i], n < g.N);
    }
    asm volatile("cp.async.commit_group;");

    for (int ch = 0; ch < 16; ch++) {
        if (ch < 15) {
            int k0 = (ch + 1) * 32;
            int boff = ((ch + 1) & 1) * 4608;
            #pragma unroll
            for (int i = 0; i < 4; i++) {
                cp16(xsa + (boff + rowi[i]*36 + kqi[i]) * 4,
                     g.X + (size_t)(bm + rowi[i]) * g.ldx + k0 + kqi[i], true);
                int n = bn + rowi[i];
                int nc = n < g.N ? n : 0;
                cp16(wsa + (boff + rowi[i]*36 + kqi[i]) * 4,
                     g.W + (size_t)nc * 512 + k0 + kqi[i], n < g.N);
            }
            asm volatile("cp.async.commit_group;");
            asm volatile("cp.async.wait_group 1;");
        } else {
            asm volatile("cp.async.wait_group 0;");
        }
        __syncthreads();

        const float* Xb = Xs + (ch & 1) * 4608;
        const float* Wb = Ws + (ch & 1) * 4608;
        #pragma unroll
        for (int ks = 0; ks < 4; ks++) {
            const int kk = ks * 8;
            uint32_t a[2][4], b[8][2];
            #pragma unroll
            for (int mt = 0; mt < 2; mt++) {
                int base = (wm + 16 * mt + lq) * 36 + kk + lr;
                a[mt][0] = SBITS(Xb, base);
                a[mt][1] = SBITS(Xb, base + 8 * 36);
                a[mt][2] = SBITS(Xb, base + 4);
                a[mt][3] = SBITS(Xb, base + 8 * 36 + 4);
            }
            #pragma unroll
            for (int nt = 0; nt < 8; nt++) {
                int base = (wn + 8 * nt + lq) * 36 + kk + lr;
                b[nt][0] = SBITS(Wb, base);
                b[nt][1] = SBITS(Wb, base + 4);
            }
            #pragma unroll
            for (int mt = 0; mt < 2; mt++)
                #pragma unroll
                for (int nt = 0; nt < 8; nt++)
                    mma_tf32(c[mt][nt], a[mt][0], a[mt][1], a[mt][2], a[mt][3],
                             b[nt][0], b[nt][1]);
        }
        __syncthreads();
    }

    #pragma unroll
    for (int mt = 0; mt < 2; mt++)
        #pragma unroll
        for (int j = 0; j < 2; j++) {
            int row = bm + wm + 16 * mt + lq + 8 * j;
            float* crow = g.C + (size_t)row * g.ldc;
            const float* mrow = g.mul ? (g.mul + (size_t)row * g.ldmul) : (const float*)0;
            #pragma unroll
            for (int nt = 0; nt < 8; nt++) {
                int col = bn + wn + 8 * nt + 2 * lr;
                if (col < g.N) {
                    float v0 = c[mt][nt][2 * j]     + g.bias[col];
                    float v1 = c[mt][nt][2 * j + 1] + g.bias[col + 1];
                    if (mrow) { v0 *= mrow[col]; v1 *= mrow[col + 1]; }
                    if (g.rnd) { v0 = to_tf32(v0); v1 = to_tf32(v1); }
                    *(float2*)(crow + col) = make_float2(v0, v1);
                }
            }
        }
}

// ---------------- depthwise conv along seq (K=9, pad 4); output tf32-rounded ------
__global__ void dwconv_kernel(const float* __restrict__ hid, const float* __restrict__ dw)
{
    int idx = blockIdx.x * blockDim.x + threadIdx.x;
    int c = idx & (AA - 1);
    int m = idx >> 9;
    int b = m >> 11, s = m & (SS - 1);
    float acc = 0.f;
    #pragma unroll
    for (int k = 0; k < KW; k++) {
        int s2 = s + k - KW / 2;
        if (s2 >= 0 && s2 < SS)
            acc = fmaf(hid[(size_t)(b * SS + s2) * HIDD + AA + c], dw[c * KW + k], acc);
    }
    g_dw[idx] = to_tf32(acc);
}

// ---------------- conv_out with inline softmax over K=9 ----------------
__global__ void convout_kernel(float* __restrict__ out)
{
    int idx = blockIdx.x * blockDim.x + threadIdx.x;
    int c = idx & (AA - 1);
    int m = idx >> 9;
    int b = m >> 11, s = m & (SS - 1);
    int h = c >> 6;
    const float* lg = g_ckl + (size_t)m * (NH * KW) + h * KW;
    float l[KW], mx = -INFINITY;
    #pragma unroll
    for (int k = 0; k < KW; k++) { l[k] = lg[k]; mx = fmaxf(mx, l[k]); }
    float sum = 0.f;
    #pragma unroll
    for (int k = 0; k < KW; k++) { l[k] = fast_exp(l[k] - mx); sum += l[k]; }
    float acc = 0.f;
    #pragma unroll
    for (int k = 0; k < KW; k++) {
        int s2 = s + k - KW / 2;
        if (s2 >= 0 && s2 < SS)
            acc = fmaf(g_col[(size_t)(b * SS + s2) * AA + c], l[k], acc);
    }
    out[(size_t)m * HIDD + AA + c] = acc / sum;
}

// ---------------- flash attention: tf32 mma + fast_exp + K/V reg-prefetch ---------
__global__ __launch_bounds__(256)
void attn_kernel(float* __restrict__ out)
{
    extern __shared__ __align__(16) float sm[];
    float* Qs = sm;                  // [128][68]
    float* Ks = Qs + 128 * 68;       // [128][76]  (76 = 12 mod 32: conflict-free)
    float* Vs = Ks + 128 * 76;       // [128][76]
    float* Pt = Vs + 128 * 76;       // [128][132]

    const int tid  = threadIdx.x;
    const int lane = tid & 31, wid = tid >> 5;
    const int lq = lane >> 2, lr = lane & 3;
    const int q0 = blockIdx.x * 128;
    const int h = blockIdx.y & (NH - 1), b = blockIdx.y >> 3;

    const float* Qg = g_q + (size_t)(b * SS) * AA + h * HD;
    const float* Kg = g_k + (size_t)(b * SS) * AA + h * HD;
    const float* Vg = g_v + (size_t)(b * SS) * AA + h * HD;

    #pragma unroll
    for (int i = 0; i < 8; i++) {
        int fl = tid + i * 256;
        int row = fl >> 4, c4 = (fl & 15) << 2;
        float4 qv = *(const float4*)(Qg + (size_t)(q0 + row) * AA + c4);
        *(float4*)&Qs[row * 68 + c4] = make_float4(
            to_tf32(qv.x * 0.125f), to_tf32(qv.y * 0.125f),
            to_tf32(qv.z * 0.125f), to_tf32(qv.w * 0.125f));
    }

    float4 kpre[8], vpre[8];
    #pragma unroll
    for (int i = 0; i < 8; i++) {
        int fl = tid + i * 256;
        int row = fl >> 4, c4 = (fl & 15) << 2;
        size_t gidx = (size_t)row * AA + c4;
        kpre[i] = *(const float4*)(Kg + gidx);
        vpre[i] = *(const float4*)(Vg + gidx);
    }

    float o[8][4];
    #pragma unroll
    for (int nt = 0; nt < 8; nt++)
        #pragma unroll
        for (int j = 0; j < 4; j++) o[nt][j] = 0.f;
    float mr[2] = {-INFINITY, -INFINITY}, lr_[2] = {0.f, 0.f};

    const int arow = wid * 16 + lq;

    for (int kt = 0; kt < 16; kt++) {
        __syncthreads();
        #pragma unroll
        for (int i = 0; i < 8; i++) {
            int fl = tid + i * 256;
            int row = fl >> 4, c4 = (fl & 15) << 2;
            *(float4*)&Ks[row * 76 + c4] = make_float4(
                to_tf32(kpre[i].x), to_tf32(kpre[i].y),
                to_tf32(kpre[i].z), to_tf32(kpre[i].w));
            *(float4*)&Vs[row * 76 + c4] = make_float4(
                to_tf32(vpre[i].x), to_tf32(vpre[i].y),
                to_tf32(vpre[i].z), to_tf32(vpre[i].w));
        }
        if (kt < 15) {
            #pragma unroll
            for (int i = 0; i < 8; i++) {
                int fl = tid + i * 256;
                int row = fl >> 4, c4 = (fl & 15) << 2;
                size_t gidx = (size_t)((kt + 1) * 128 + row) * AA + c4;
                kpre[i] = *(const float4*)(Kg + gidx);
                vpre[i] = *(const float4*)(Vg + gidx);
            }
        }
        __syncthreads();

        float s[16][4];
        #pragma unroll
        for (int nt = 0; nt < 16; nt++)
            #pragma unroll
            for (int j = 0; j < 4; j++) s[nt][j] = 0.f;

        #pragma unroll
        for (int ks = 0; ks < 8; ks++) {
            const int kk = ks * 8;
            int abase = arow * 68 + kk + lr;
            uint32_t a0 = SBITS(Qs, abase);
            uint32_t a1 = SBITS(Qs, abase + 8 * 68);
            uint32_t a2 = SBITS(Qs, abase + 4);
            uint32_t a3 = SBITS(Qs, abase + 8 * 68 + 4);
            #pragma unroll
            for (int nt = 0; nt < 16; nt++) {
                int bbase = (8 * nt + lq) * 76 + kk + lr;
                mma_tf32(s[nt], a0, a1, a2, a3, SBITS(Ks, bbase), SBITS(Ks, bbase + 4));
            }
        }

        #pragma unroll
        for (int j = 0; j < 2; j++) {
            float tm = -INFINITY;
            #pragma unroll
            for (int nt = 0; nt < 16; nt++)
                tm = fmaxf(tm, fmaxf(s[nt][2*j], s[nt][2*j+1]));
            tm = fmaxf(tm, __shfl_xor_sync(0xffffffffu, tm, 1));
            tm = fmaxf(tm, __shfl_xor_sync(0xffffffffu, tm, 2));
            float mnew = fmaxf(mr[j], tm);
            float alpha = fast_exp(mr[j] - mnew);
            float sum = 0.f;
            #pragma unroll
            for (int nt = 0; nt < 16; nt++) {
                float e0 = fast_exp(s[nt][2*j]   - mnew);
                float e1 = fast_exp(s[nt][2*j+1] - mnew);
                sum += e0 + e1;
                s[nt][2*j]   = to_tf32(e0);
                s[nt][2*j+1] = to_tf32(e1);
            }
            sum += __shfl_xor_sync(0xffffffffu, sum, 1);
            sum += __shfl_xor_sync(0xffffffffu, sum, 2);
            lr_[j] = lr_[j] * alpha + sum;
            mr[j] = mnew;
            #pragma unroll
            for (int nt = 0; nt < 8; nt++) {
                o[nt][2*j]   *= alpha;
                o[nt][2*j+1] *= alpha;
            }
        }

        #pragma unroll
        for (int j = 0; j < 2; j++)
            #pragma unroll
            for (int nt = 0; nt < 16; nt++)
                *(float2*)&Pt[(arow + 8*j) * 132 + 8*nt + 2*lr] =
                    make_float2(s[nt][2*j], s[nt][2*j+1]);
        __syncwarp();

        #pragma unroll
        for (int kk2 = 0; kk2 < 16; kk2++) {
            const int k0 = 8 * kk2;
            int abase = arow * 132 + k0 + lr;
            uint32_t a0 = SBITS(Pt, abase);
            uint32_t a1 = SBITS(Pt, abase + 8 * 132);
            uint32_t a2 = SBITS(Pt, abase + 4);
            uint32_t a3 = SBITS(Pt, abase + 8 * 132 + 4);
            #pragma unroll
            for (int nt = 0; nt < 8; nt++) {
                int bbase = (k0 + lr) * 76 + 8 * nt + lq;
                mma_tf32(o[nt], a0, a1, a2, a3, SBITS(Vs, bbase), SBITS(Vs, bbase + 4 * 76));
            }
        }
    }

    #pragma unroll
    for (int j = 0; j < 2; j++) {
        float inv = 1.f / lr_[j];
        size_t row = (size_t)(b * SS + q0 + arow + 8 * j);
        #pragma unroll
        for (int nt = 0; nt < 8; nt++) {
            int col = h * HD + 8 * nt + 2 * lr;
            *(float2*)&out[row * HIDD + col] =
                make_float2(o[nt][2*j] * inv, o[nt][2*j+1] * inv);
        }
    }
}

// ---------------- launch ----------------
extern "C" void kernel_launch(void* const* d_in, const int* in_sizes, int n_in,
                              void* d_out, int out_size)
{
    const float* hid  = (const float*)d_in[0];
    const float* Wq   = (const float*)d_in[1];
    const float* bq   = (const float*)d_in[2];
    const float* Wk   = (const float*)d_in[3];
    const float* bk   = (const float*)d_in[4];
    const float* Wv   = (const float*)d_in[5];
    const float* bv   = (const float*)d_in[6];
    const float* dww  = (const float*)d_in[7];
    const float* pww  = (const float*)d_in[8];
    const float* sepb = (const float*)d_in[9];
    const float* Wck  = (const float*)d_in[10];
    const float* bck  = (const float*)d_in[11];
    const float* Wco  = (const float*)d_in[12];
    const float* bco  = (const float*)d_in[13];
    float* out = (float*)d_out;

    float *qp, *kp, *vp, *colp, *dwp, *cap, *cklp, *hidp, *wbp;
    cudaGetSymbolAddress((void**)&qp,   g_q);
    cudaGetSymbolAddress((void**)&kp,   g_k);
    cudaGetSymbolAddress((void**)&vp,   g_v);
    cudaGetSymbolAddress((void**)&colp, g_col);
    cudaGetSymbolAddress((void**)&dwp,  g_dw);
    cudaGetSymbolAddress((void**)&cap,  g_ca);
    cudaGetSymbolAddress((void**)&cklp, g_ckl);
    cudaGetSymbolAddress((void**)&hidp, g_hid);
    cudaGetSymbolAddress((void**)&wbp,  g_wbuf);

    const int GEMM_SMEM = 4 * 4608 * 4;                            // 73728
    const int ATTN_SMEM = (128*68 + 128*76*2 + 128*132) * 4;       // 180224
    cudaFuncSetAttribute(gemm_kernel, cudaFuncAttributeMaxDynamicSharedMemorySize, GEMM_SMEM);
    cudaFuncSetAttribute(attn_kernel, cudaFuncAttributeMaxDynamicSharedMemorySize, ATTN_SMEM);

    const int WSZ = AA * AA;

    CArgs ca;
    ca.s[0] = { hid, hidp,           MM * HIDD / 4 };
    ca.s[1] = { Wq,  wbp + 0 * WSZ,  WSZ / 4 };
    ca.s[2] = { Wk,  wbp + 1 * WSZ,  WSZ / 4 };
    ca.s[3] = { Wv,  wbp + 2 * WSZ,  WSZ / 4 };
    ca.s[4] = { Wco, wbp + 3 * WSZ,  WSZ / 4 };
    ca.s[5] = { pww, wbp + 4 * WSZ,  WSZ / 4 };
    ca.s[6] = { Wck, wbp + 5 * WSZ,  NH * KW * AA / 4 };
    cvt_kernel<<<dim3(512, 1, 7), 256>>>(ca);

    GArgs g1;
    g1.s[0] = { hidp,      wbp + 0*WSZ, bq,  nullptr, qp,   HIDD, 0, AA, AA, 0 };
    g1.s[1] = { hidp,      wbp + 1*WSZ, bk,  nullptr, kp,   HIDD, 0, AA, AA, 0 };
    g1.s[2] = { hidp,      wbp + 2*WSZ, bv,  nullptr, vp,   HIDD, 0, AA, AA, 0 };
    g1.s[3] = { hidp + AA, wbp + 3*WSZ, bco, nullptr, colp, HIDD, 0, AA, AA, 0 };
    gemm_kernel<<<dim3(4, 64, 4), 256, GEMM_SMEM>>>(g1);

    dwconv_kernel<<<MM * AA / 256, 256>>>(hid, dww);

    GArgs g2;
    g2.s[0] = { dwp, wbp + 4*WSZ, sepb, hid + AA, cap, AA, HIDD, AA, AA, 1 };
    gemm_kernel<<<dim3(4, 64, 1), 256, GEMM_SMEM>>>(g2);

    GArgs g3;
    g3.s[0] = { cap, wbp + 5*WSZ, bck, nullptr, cklp, AA, 0, NH*KW, NH*KW, 0 };
    gemm_kernel<<<dim3(1, 64, 1), 256, GEMM_SMEM>>>(g3);

    convout_kernel<<<MM * AA / 256, 256>>>(out);

    attn_kernel<<<dim3(SS / 128, BB * NH), 256, ATTN_SMEM>>>(out);
}

// round 6
// speedup vs baseline: 5.4237x; 1.4084x over previous
#include <cuda_runtime.h>
#include <cuda_fp16.h>
#include <math.h>
#include <stdint.h>

#define NH   8
#define HD   64
#define KW   9
#define AA   512
#define HIDD 1024
#define BB   4
#define SS   2048
#define MM   (BB*SS)   // 8192

// ---------------- scratch (device globals; no allocation) ----------------
__device__ float g_q[MM*AA];
__device__ float g_k[MM*AA];
__device__ float g_v[MM*AA];
__device__ float g_col[MM*AA];
__device__ float g_dw[MM*AA];
__device__ float g_ca[MM*AA];
__device__ float g_ckl[MM*NH*KW];
__device__ float g_hid[MM*HIDD];                    // tf32-rounded hidden_states
__device__ float g_wbuf[5*AA*AA + NH*KW*AA];        // tf32-rounded weights

// ---------------- helpers ----------------
__device__ __forceinline__ float to_tf32(float x) {
    asm("cvt.rna.tf32.f32 %0, %1;" : "=f"(x) : "f"(x));
    return x;
}

__device__ __forceinline__ void mma_tf32(float c[4],
    uint32_t a0, uint32_t a1, uint32_t a2, uint32_t a3,
    uint32_t b0, uint32_t b1)
{
    asm volatile("mma.sync.aligned.m16n8k8.row.col.f32.tf32.tf32.f32 "
        "{%0,%1,%2,%3}, {%4,%5,%6,%7}, {%8,%9}, {%0,%1,%2,%3};"
        : "+f"(c[0]), "+f"(c[1]), "+f"(c[2]), "+f"(c[3])
        : "r"(a0), "r"(a1), "r"(a2), "r"(a3), "r"(b0), "r"(b1));
}

__device__ __forceinline__ void mma_f16(float c[4],
    uint32_t a0, uint32_t a1, uint32_t a2, uint32_t a3,
    uint32_t b0, uint32_t b1)
{
    asm volatile("mma.sync.aligned.m16n8k16.row.col.f32.f16.f16.f32 "
        "{%0,%1,%2,%3}, {%4,%5,%6,%7}, {%8,%9}, {%0,%1,%2,%3};"
        : "+f"(c[0]), "+f"(c[1]), "+f"(c[2]), "+f"(c[3])
        : "r"(a0), "r"(a1), "r"(a2), "r"(a3), "r"(b0), "r"(b1));
}

// fast exp on FMA pipe (avoids MUFU bottleneck). x <= 0 expected; handles -inf.
__device__ __forceinline__ float fast_exp(float x) {
    float t = fmaxf(x * 1.4426950408889634f, -126.0f);
    float z = t + 12582912.0f;
    int   n = __float_as_int(z) - 0x4B400000;
    float r = t - (z - 12582912.0f);
    float p = fmaf(r, 0.009618129f, 0.055504109f);
    p = fmaf(r, p, 0.240226507f);
    p = fmaf(r, p, 0.693147181f);
    p = fmaf(r, p, 1.0f);
    return __int_as_float(__float_as_int(p) + (n << 23));
}

__device__ __forceinline__ void cp16(uint32_t saddr, const void* g, bool pred) {
    asm volatile("cp.async.ca.shared.global [%0], [%1], 16, %2;"
                 :: "r"(saddr), "l"(g), "r"(pred ? 16u : 0u));
}

__device__ __forceinline__ uint32_t packh2(float a, float b) {
    __half2 h = __floats2half2_rn(a, b);
    return *(uint32_t*)&h;
}

#define SBITS(arr, idx) (*(const uint32_t*)&(arr)[idx])

// ---------------- tf32 pre-rounding pass ----------------
struct CSlot { const float* src; float* dst; int n4; };
struct CArgs { CSlot s[7]; };

__global__ void cvt_kernel(CArgs a)
{
    CSlot c = a.s[blockIdx.z];
    const float4* src = (const float4*)c.src;
    float4* dst = (float4*)c.dst;
    for (int i = blockIdx.x * blockDim.x + threadIdx.x; i < c.n4;
         i += gridDim.x * blockDim.x) {
        float4 v = src[i];
        dst[i] = make_float4(to_tf32(v.x), to_tf32(v.y), to_tf32(v.z), to_tf32(v.w));
    }
}

// ---------------- tf32 tensor-core GEMM, cp.async double-buffered ----------------
struct GSlot {
    const float* X; const float* W; const float* bias; const float* mul;
    float* C; int ldx; int ldmul; int ldc; int N; int rnd;
};
struct GArgs { GSlot s[4]; };

__global__ __launch_bounds__(256, 2)
void gemm_kernel(GArgs args)
{
    GSlot g = args.s[blockIdx.z];
    extern __shared__ __align__(16) float smg[];
    float* Xs = smg;                 // [2][128*36]
    float* Ws = smg + 2 * 4608;      // [2][128*36]

    const int tid  = threadIdx.x;
    const int lane = tid & 31, wid = tid >> 5;
    const int wm = (wid >> 1) * 32, wn = (wid & 1) * 64;
    const int bm = blockIdx.y * 128, bn = blockIdx.x * 128;
    const int lq = lane >> 2, lr = lane & 3;

    int rowi[4], kqi[4];
    #pragma unroll
    for (int i = 0; i < 4; i++) {
        int fl = tid + i * 256;
        rowi[i] = fl >> 3;
        kqi[i]  = (fl & 7) << 2;
    }
    const uint32_t xsa = (uint32_t)__cvta_generic_to_shared(Xs);
    const uint32_t wsa = (uint32_t)__cvta_generic_to_shared(Ws);

    float c[2][8][4];
    #pragma unroll
    for (int mt = 0; mt < 2; mt++)
        #pragma unroll
        for (int nt = 0; nt < 8; nt++)
            #pragma unroll
            for (int j = 0; j < 4; j++) c[mt][nt][j] = 0.f;

    #pragma unroll
    for (int i = 0; i < 4; i++) {
        cp16(xsa + (rowi[i]*36 + kqi[i]) * 4,
             g.X + (size_t)(bm + rowi[i]) * g.ldx + kqi[i], true);
        int n = bn + rowi[i];
        int nc = n < g.N ? n : 0;
        cp16(wsa + (rowi[i]*36 + kqi[i]) * 4,
             g.W + (size_t)nc * 512 + kqi[i], n < g.N);
    }
    asm volatile("cp.async.commit_group;");

    for (int ch = 0; ch < 16; ch++) {
        if (ch < 15) {
            int k0 = (ch + 1) * 32;
            int boff = ((ch + 1) & 1) * 4608;
            #pragma unroll
            for (int i = 0; i < 4; i++) {
                cp16(xsa + (boff + rowi[i]*36 + kqi[i]) * 4,
                     g.X + (size_t)(bm + rowi[i]) * g.ldx + k0 + kqi[i], true);
                int n = bn + rowi[i];
                int nc = n < g.N ? n : 0;
                cp16(wsa + (boff + rowi[i]*36 + kqi[i]) * 4,
                     g.W + (size_t)nc * 512 + k0 + kqi[i], n < g.N);
            }
            asm volatile("cp.async.commit_group;");
            asm volatile("cp.async.wait_group 1;");
        } else {
            asm volatile("cp.async.wait_group 0;");
        }
        __syncthreads();

        const float* Xb = Xs + (ch & 1) * 4608;
        const float* Wb = Ws + (ch & 1) * 4608;
        #pragma unroll
        for (int ks = 0; ks < 4; ks++) {
            const int kk = ks * 8;
            uint32_t a[2][4], b[8][2];
            #pragma unroll
            for (int mt = 0; mt < 2; mt++) {
                int base = (wm + 16 * mt + lq) * 36 + kk + lr;
                a[mt][0] = SBITS(Xb, base);
                a[mt][1] = SBITS(Xb, base + 8 * 36);
                a[mt][2] = SBITS(Xb, base + 4);
                a[mt][3] = SBITS(Xb, base + 8 * 36 + 4);
            }
            #pragma unroll
            for (int nt = 0; nt < 8; nt++) {
                int base = (wn + 8 * nt + lq) * 36 + kk + lr;
                b[nt][0] = SBITS(Wb, base);
                b[nt][1] = SBITS(Wb, base + 4);
            }
            #pragma unroll
            for (int mt = 0; mt < 2; mt++)
                #pragma unroll
                for (int nt = 0; nt < 8; nt++)
                    mma_tf32(c[mt][nt], a[mt][0], a[mt][1], a[mt][2], a[mt][3],
                             b[nt][0], b[nt][1]);
        }
        __syncthreads();
    }

    #pragma unroll
    for (int mt = 0; mt < 2; mt++)
        #pragma unroll
        for (int j = 0; j < 2; j++) {
            int row = bm + wm + 16 * mt + lq + 8 * j;
            float* crow = g.C + (size_t)row * g.ldc;
            const float* mrow = g.mul ? (g.mul + (size_t)row * g.ldmul) : (const float*)0;
            #pragma unroll
            for (int nt = 0; nt < 8; nt++) {
                int col = bn + wn + 8 * nt + 2 * lr;
                if (col < g.N) {
                    float v0 = c[mt][nt][2 * j]     + g.bias[col];
                    float v1 = c[mt][nt][2 * j + 1] + g.bias[col + 1];
                    if (mrow) { v0 *= mrow[col]; v1 *= mrow[col + 1]; }
                    if (g.rnd) { v0 = to_tf32(v0); v1 = to_tf32(v1); }
                    *(float2*)(crow + col) = make_float2(v0, v1);
                }
            }
        }
}

// ---------------- depthwise conv along seq (K=9, pad 4); output tf32-rounded ------
__global__ void dwconv_kernel(const float* __restrict__ hid, const float* __restrict__ dw)
{
    int idx = blockIdx.x * blockDim.x + threadIdx.x;
    int c = idx & (AA - 1);
    int m = idx >> 9;
    int b = m >> 11, s = m & (SS - 1);
    float acc = 0.f;
    #pragma unroll
    for (int k = 0; k < KW; k++) {
        int s2 = s + k - KW / 2;
        if (s2 >= 0 && s2 < SS)
            acc = fmaf(hid[(size_t)(b * SS + s2) * HIDD + AA + c], dw[c * KW + k], acc);
    }
    g_dw[idx] = to_tf32(acc);
}

// ---------------- conv_out with inline softmax over K=9 ----------------
__global__ void convout_kernel(float* __restrict__ out)
{
    int idx = blockIdx.x * blockDim.x + threadIdx.x;
    int c = idx & (AA - 1);
    int m = idx >> 9;
    int b = m >> 11, s = m & (SS - 1);
    int h = c >> 6;
    const float* lg = g_ckl + (size_t)m * (NH * KW) + h * KW;
    float l[KW], mx = -INFINITY;
    #pragma unroll
    for (int k = 0; k < KW; k++) { l[k] = lg[k]; mx = fmaxf(mx, l[k]); }
    float sum = 0.f;
    #pragma unroll
    for (int k = 0; k < KW; k++) { l[k] = fast_exp(l[k] - mx); sum += l[k]; }
    float acc = 0.f;
    #pragma unroll
    for (int k = 0; k < KW; k++) {
        int s2 = s + k - KW / 2;
        if (s2 >= 0 && s2 < SS)
            acc = fmaf(g_col[(size_t)(b * SS + s2) * AA + c], l[k], acc);
    }
    out[(size_t)m * HIDD + AA + c] = acc / sum;
}

// ---------------- flash attention v2: tf32 QK + f16 PV (register P reuse) ---------
// 128 q-rows/CTA, 8 warps (16 rows each). 128-key tiles processed as 2x64-key
// halves (keeps S in 32 regs -> 2 CTAs/SM). P goes accumulator->A-fragment in
// registers (no smem). V stored as half [key][72], B-frags via ldmatrix.x4.trans.
__global__ __launch_bounds__(256, 2)
void attn_kernel(float* __restrict__ out)
{
    extern __shared__ __align__(16) float sm[];
    float*  Qs = sm;                          // [128][68] f32 (scaled, tf32)
    float*  Ks = Qs + 128 * 68;               // [128][76] f32 (tf32)
    __half* Vh = (__half*)(Ks + 128 * 76);    // [128][72] half

    const int tid  = threadIdx.x;
    const int lane = tid & 31, wid = tid >> 5;
    const int lq = lane >> 2, lr = lane & 3;
    const int q0 = blockIdx.x * 128;
    const int h = blockIdx.y & (NH - 1), b = blockIdx.y >> 3;

    const float* Qg = g_q + (size_t)(b * SS) * AA + h * HD;
    const float* Kg = g_k + (size_t)(b * SS) * AA + h * HD;
    const float* Vg = g_v + (size_t)(b * SS) * AA + h * HD;

    const uint32_t ksa = (uint32_t)__cvta_generic_to_shared(Ks);
    const uint32_t vha = (uint32_t)__cvta_generic_to_shared(Vh);

    // load Q (128x64), scale by 1/8 (exact; g_q already tf32-rounded)
    #pragma unroll
    for (int i = 0; i < 8; i++) {
        int fl = tid + i * 256;
        int row = fl >> 4, c4 = (fl & 15) << 2;
        float4 qv = *(const float4*)(Qg + (size_t)(q0 + row) * AA + c4);
        *(float4*)&Qs[row * 68 + c4] = make_float4(
            qv.x * 0.125f, qv.y * 0.125f, qv.z * 0.125f, qv.w * 0.125f);
    }

    float o[8][4];
    #pragma unroll
    for (int nt = 0; nt < 8; nt++)
        #pragma unroll
        for (int j = 0; j < 4; j++) o[nt][j] = 0.f;
    float mr[2] = {-INFINITY, -INFINITY}, l_[2] = {0.f, 0.f};

    const int arow = wid * 16 + lq;

    // ldmatrix lane address components (fixed per thread)
    const int lm_krow = (lane & 7) + 8 * ((lane >> 3) & 1);
    const int lm_nt2  = (lane >> 4) & 1;

    for (int kt = 0; kt < 16; kt++) {
        __syncthreads();
        // K tile via cp.async (g_k is pre-rounded tf32)
        #pragma unroll
        for (int i = 0; i < 8; i++) {
            int fl = tid + i * 256;
            int row = fl >> 4, c4 = (fl & 15) << 2;
            cp16(ksa + (row * 76 + c4) * 4,
                 Kg + (size_t)(kt * 128 + row) * AA + c4, true);
        }
        asm volatile("cp.async.commit_group;");
        // V tile: LDG f32 -> half -> smem [key][d]
        #pragma unroll
        for (int i = 0; i < 8; i++) {
            int fl = tid + i * 256;
            int row = fl >> 4, c4 = (fl & 15) << 2;
            float4 vv = *(const float4*)(Vg + (size_t)(kt * 128 + row) * AA + c4);
            uint2 pk = make_uint2(packh2(vv.x, vv.y), packh2(vv.z, vv.w));
            *(uint2*)&Vh[row * 72 + c4] = pk;
        }
        asm volatile("cp.async.wait_group 0;");
        __syncthreads();

        #pragma unroll
        for (int h2 = 0; h2 < 2; h2++) {
            // S = Q K^T for 64 keys
            float s[8][4];
            #pragma unroll
            for (int nt = 0; nt < 8; nt++)
                #pragma unroll
                for (int j = 0; j < 4; j++) s[nt][j] = 0.f;

            #pragma unroll
            for (int ks = 0; ks < 8; ks++) {
                const int kk = ks * 8;
                int abase = arow * 68 + kk + lr;
                uint32_t a0 = SBITS(Qs, abase);
                uint32_t a1 = SBITS(Qs, abase + 8 * 68);
                uint32_t a2 = SBITS(Qs, abase + 4);
                uint32_t a3 = SBITS(Qs, abase + 8 * 68 + 4);
                #pragma unroll
                for (int nt = 0; nt < 8; nt++) {
                    int bbase = (h2 * 64 + 8 * nt + lq) * 76 + kk + lr;
                    mma_tf32(s[nt], a0, a1, a2, a3,
                             SBITS(Ks, bbase), SBITS(Ks, bbase + 4));
                }
            }

            // online softmax update (thread rows arow, arow+8; 4 lanes/row)
            #pragma unroll
            for (int j = 0; j < 2; j++) {
                float tm = -INFINITY;
                #pragma unroll
                for (int nt = 0; nt < 8; nt++)
                    tm = fmaxf(tm, fmaxf(s[nt][2*j], s[nt][2*j+1]));
                tm = fmaxf(tm, __shfl_xor_sync(0xffffffffu, tm, 1));
                tm = fmaxf(tm, __shfl_xor_sync(0xffffffffu, tm, 2));
                float mnew = fmaxf(mr[j], tm);
                float alpha = fast_exp(mr[j] - mnew);
                float sum = 0.f;
                #pragma unroll
                for (int nt = 0; nt < 8; nt++) {
                    float e0 = fast_exp(s[nt][2*j]   - mnew);
                    float e1 = fast_exp(s[nt][2*j+1] - mnew);
                    sum += e0 + e1;
                    s[nt][2*j]   = e0;
                    s[nt][2*j+1] = e1;
                }
                sum += __shfl_xor_sync(0xffffffffu, sum, 1);
                sum += __shfl_xor_sync(0xffffffffu, sum, 2);
                l_[j] = l_[j] * alpha + sum;
                mr[j] = mnew;
                #pragma unroll
                for (int nt = 0; nt < 8; nt++) {
                    o[nt][2*j]   *= alpha;
                    o[nt][2*j+1] *= alpha;
                }
            }

            // O += P @ V : P from registers (accum layout == f16 A-frag layout)
            #pragma unroll
            for (int t = 0; t < 4; t++) {
                uint32_t pa0 = packh2(s[2*t][0],   s[2*t][1]);
                uint32_t pa1 = packh2(s[2*t][2],   s[2*t][3]);
                uint32_t pa2 = packh2(s[2*t+1][0], s[2*t+1][1]);
                uint32_t pa3 = packh2(s[2*t+1][2], s[2*t+1][3]);
                const int kbase = h2 * 64 + 16 * t;
                #pragma unroll
                for (int ntp = 0; ntp < 4; ntp++) {
                    uint32_t addr = vha +
                        ((kbase + lm_krow) * 72 + 8 * (2 * ntp + lm_nt2)) * 2;
                    uint32_t b0, b1, b2, b3;
                    asm volatile(
                        "ldmatrix.sync.aligned.m8n8.x4.trans.shared.b16 "
                        "{%0,%1,%2,%3}, [%4];"
                        : "=r"(b0), "=r"(b1), "=r"(b2), "=r"(b3) : "r"(addr));
                    mma_f16(o[2*ntp],     pa0, pa1, pa2, pa3, b0, b1);
                    mma_f16(o[2*ntp + 1], pa0, pa1, pa2, pa3, b2, b3);
                }
            }
        }
    }

    // epilogue
    #pragma unroll
    for (int j = 0; j < 2; j++) {
        float inv = 1.f / l_[j];
        size_t row = (size_t)(b * SS + q0 + arow + 8 * j);
        #pragma unroll
        for (int nt = 0; nt < 8; nt++) {
            int col = h * HD + 8 * nt + 2 * lr;
            *(float2*)&out[row * HIDD + col] =
                make_float2(o[nt][2*j] * inv, o[nt][2*j+1] * inv);
        }
    }
}

// ---------------- launch ----------------
extern "C" void kernel_launch(void* const* d_in, const int* in_sizes, int n_in,
                              void* d_out, int out_size)
{
    const float* hid  = (const float*)d_in[0];
    const float* Wq   = (const float*)d_in[1];
    const float* bq   = (const float*)d_in[2];
    const float* Wk   = (const float*)d_in[3];
    const float* bk   = (const float*)d_in[4];
    const float* Wv   = (const float*)d_in[5];
    const float* bv   = (const float*)d_in[6];
    const float* dww  = (const float*)d_in[7];
    const float* pww  = (const float*)d_in[8];
    const float* sepb = (const float*)d_in[9];
    const float* Wck  = (const float*)d_in[10];
    const float* bck  = (const float*)d_in[11];
    const float* Wco  = (const float*)d_in[12];
    const float* bco  = (const float*)d_in[13];
    float* out = (float*)d_out;

    float *qp, *kp, *vp, *colp, *dwp, *cap, *cklp, *hidp, *wbp;
    cudaGetSymbolAddress((void**)&qp,   g_q);
    cudaGetSymbolAddress((void**)&kp,   g_k);
    cudaGetSymbolAddress((void**)&vp,   g_v);
    cudaGetSymbolAddress((void**)&colp, g_col);
    cudaGetSymbolAddress((void**)&dwp,  g_dw);
    cudaGetSymbolAddress((void**)&cap,  g_ca);
    cudaGetSymbolAddress((void**)&cklp, g_ckl);
    cudaGetSymbolAddress((void**)&hidp, g_hid);
    cudaGetSymbolAddress((void**)&wbp,  g_wbuf);

    const int GEMM_SMEM = 4 * 4608 * 4;                             // 73728
    const int ATTN_SMEM = (128*68 + 128*76) * 4 + 128*72*2;         // 92160
    cudaFuncSetAttribute(gemm_kernel, cudaFuncAttributeMaxDynamicSharedMemorySize, GEMM_SMEM);
    cudaFuncSetAttribute(attn_kernel, cudaFuncAttributeMaxDynamicSharedMemorySize, ATTN_SMEM);

    const int WSZ = AA * AA;

    CArgs ca;
    ca.s[0] = { hid, hidp,           MM * HIDD / 4 };
    ca.s[1] = { Wq,  wbp + 0 * WSZ,  WSZ / 4 };
    ca.s[2] = { Wk,  wbp + 1 * WSZ,  WSZ / 4 };
    ca.s[3] = { Wv,  wbp + 2 * WSZ,  WSZ / 4 };
    ca.s[4] = { Wco, wbp + 3 * WSZ,  WSZ / 4 };
    ca.s[5] = { pww, wbp + 4 * WSZ,  WSZ / 4 };
    ca.s[6] = { Wck, wbp + 5 * WSZ,  NH * KW * AA / 4 };
    cvt_kernel<<<dim3(512, 1, 7), 256>>>(ca);

    GArgs g1;   // q,k tf32-rounded outputs (enables raw cp.async in attention)
    g1.s[0] = { hidp,      wbp + 0*WSZ, bq,  nullptr, qp,   HIDD, 0, AA, AA, 1 };
    g1.s[1] = { hidp,      wbp + 1*WSZ, bk,  nullptr, kp,   HIDD, 0, AA, AA, 1 };
    g1.s[2] = { hidp,      wbp + 2*WSZ, bv,  nullptr, vp,   HIDD, 0, AA, AA, 0 };
    g1.s[3] = { hidp + AA, wbp + 3*WSZ, bco, nullptr, colp, HIDD, 0, AA, AA, 0 };
    gemm_kernel<<<dim3(4, 64, 4), 256, GEMM_SMEM>>>(g1);

    dwconv_kernel<<<MM * AA / 256, 256>>>(hid, dww);

    GArgs g2;
    g2.s[0] = { dwp, wbp + 4*WSZ, sepb, hid + AA, cap, AA, HIDD, AA, AA, 1 };
    gemm_kernel<<<dim3(4, 64, 1), 256, GEMM_SMEM>>>(g2);

    GArgs g3;
    g3.s[0] = { cap, wbp + 5*WSZ, bck, nullptr, cklp, AA, 0, NH*KW, NH*KW, 0 };
    gemm_kernel<<<dim3(1, 64, 1), 256, GEMM_SMEM>>>(g3);

    convout_kernel<<<MM * AA / 256, 256>>>(out);

    attn_kernel<<<dim3(SS / 128, BB * NH), 256, ATTN_SMEM>>>(out);
}

// round 8
// speedup vs baseline: 7.3022x; 1.3464x over previous
#include <cuda_runtime.h>
#include <cuda_fp16.h>
#include <math.h>
#include <stdint.h>

#define NH   8
#define HD   64
#define KW   9
#define AA   512
#define HIDD 1024
#define BB   4
#define SS   2048
#define MM   (BB*SS)   // 8192

// ---------------- scratch (device globals; no allocation) ----------------
__device__ __half g_qh[MM*AA];                   // q * 0.125, half
__device__ __half g_kh[MM*AA];
__device__ __half g_vh[MM*AA];
__device__ __half g_dwh[MM*AA];                  // depthwise conv out, half
__device__ __half g_cah[MM*AA];                  // conv_attn, half
__device__ __half g_hidh[MM*HIDD];               // hidden_states, half
__device__ __half g_wh[5*AA*AA + NH*KW*AA];      // weights, half
__device__ float  g_col[MM*AA];
__device__ float  g_ckl[MM*NH*KW];

// ---------------- helpers ----------------
__device__ __forceinline__ void mma_f16(float c[4],
    uint32_t a0, uint32_t a1, uint32_t a2, uint32_t a3,
    uint32_t b0, uint32_t b1)
{
    asm volatile("mma.sync.aligned.m16n8k16.row.col.f32.f16.f16.f32 "
        "{%0,%1,%2,%3}, {%4,%5,%6,%7}, {%8,%9}, {%0,%1,%2,%3};"
        : "+f"(c[0]), "+f"(c[1]), "+f"(c[2]), "+f"(c[3])
        : "r"(a0), "r"(a1), "r"(a2), "r"(a3), "r"(b0), "r"(b1));
}

__device__ __forceinline__ void ldsm4(uint32_t& r0, uint32_t& r1,
                                      uint32_t& r2, uint32_t& r3, uint32_t addr)
{
    asm volatile("ldmatrix.sync.aligned.m8n8.x4.shared.b16 {%0,%1,%2,%3}, [%4];"
        : "=r"(r0), "=r"(r1), "=r"(r2), "=r"(r3) : "r"(addr));
}

__device__ __forceinline__ void ldsm4t(uint32_t& r0, uint32_t& r1,
                                       uint32_t& r2, uint32_t& r3, uint32_t addr)
{
    asm volatile("ldmatrix.sync.aligned.m8n8.x4.trans.shared.b16 {%0,%1,%2,%3}, [%4];"
        : "=r"(r0), "=r"(r1), "=r"(r2), "=r"(r3) : "r"(addr));
}

// fast exp on FMA pipe. x <= 0 expected; handles -inf.
__device__ __forceinline__ float fast_exp(float x) {
    float t = fmaxf(x * 1.4426950408889634f, -126.0f);
    float z = t + 12582912.0f;
    int   n = __float_as_int(z) - 0x4B400000;
    float r = t - (z - 12582912.0f);
    float p = fmaf(r, 0.009618129f, 0.055504109f);
    p = fmaf(r, p, 0.240226507f);
    p = fmaf(r, p, 0.693147181f);
    p = fmaf(r, p, 1.0f);
    return __int_as_float(__float_as_int(p) + (n << 23));
}

__device__ __forceinline__ void cp16(uint32_t saddr, const void* g, bool pred) {
    asm volatile("cp.async.ca.shared.global [%0], [%1], 16, %2;"
                 :: "r"(saddr), "l"(g), "r"(pred ? 16u : 0u));
}

__device__ __forceinline__ uint32_t packh2(float a, float b) {
    __half2 h = __floats2half2_rn(a, b);
    return *(uint32_t*)&h;
}

// ---------------- f32 -> f16 conversion pass ----------------
struct CSlot { const float* src; __half* dst; int n4; };
struct CArgs { CSlot s[7]; };

__global__ void cvt_kernel(CArgs a)
{
    CSlot c = a.s[blockIdx.z];
    const float4* src = (const float4*)c.src;
    for (int i = blockIdx.x * blockDim.x + threadIdx.x; i < c.n4;
         i += gridDim.x * blockDim.x) {
        float4 v = src[i];
        uint2 pk = make_uint2(packh2(v.x, v.y), packh2(v.z, v.w));
        *(uint2*)(c.dst + (size_t)i * 4) = pk;
    }
}

// ---------------- f16 tensor-core GEMM, cp.async double-buffered ----------------
// C[M,N] = X[M,512] @ W[N,512]^T + bias  (optional *mul f32; out f32 or half*osc)
// 128x128 tile, BK=32 x2 buffers, 256 threads (8 warps 4x2), warp tile 32x64.
struct GSlot {
    const __half* X; const __half* W; const float* bias; const float* mul;
    void* C; int ldx; int ldmul; int ldc; int N; int outHalf; float osc;
};
struct GArgs { GSlot s[4]; };

__global__ __launch_bounds__(256, 2)
void gemm_kernel(GArgs args)
{
    GSlot g = args.s[blockIdx.z];
    extern __shared__ __align__(16) __half smh[];
    __half* Xs = smh;                  // [2][128*40]
    __half* Ws = smh + 2 * 5120;       // [2][128*40]

    const int tid  = threadIdx.x;
    const int lane = tid & 31, wid = tid >> 5;
    const int wm = (wid >> 1) * 32, wn = (wid & 1) * 64;
    const int bm = blockIdx.y * 128, bn = blockIdx.x * 128;
    const int lr = lane & 3;
    const int lm_row = (lane & 7) + 8 * ((lane >> 3) & 1);  // ldmatrix row sel
    const int lm_hi  = lane >> 4;                           // k-half sel

    const uint32_t xsa = (uint32_t)__cvta_generic_to_shared(Xs);
    const uint32_t wsa = (uint32_t)__cvta_generic_to_shared(Ws);

    // staging: BK=32 halfs/row -> 4x16B chunks/row, 128 rows = 512 chunks, 2 iters
    int srow[2], sc8[2];
    #pragma unroll
    for (int i = 0; i < 2; i++) {
        int fl = tid + i * 256;
        srow[i] = fl >> 2;
        sc8[i]  = (fl & 3) << 3;
    }

    float c[2][8][4];
    #pragma unroll
    for (int mt = 0; mt < 2; mt++)
        #pragma unroll
        for (int nt = 0; nt < 8; nt++)
            #pragma unroll
            for (int j = 0; j < 4; j++) c[mt][nt][j] = 0.f;

    // stage chunk 0
    #pragma unroll
    for (int i = 0; i < 2; i++) {
        cp16(xsa + (srow[i]*40 + sc8[i]) * 2,
             g.X + (size_t)(bm + srow[i]) * g.ldx + sc8[i], true);
        int n = bn + srow[i];
        int nc = n < g.N ? n : 0;
        cp16(wsa + (srow[i]*40 + sc8[i]) * 2,
             g.W + (size_t)nc * 512 + sc8[i], n < g.N);
    }
    asm volatile("cp.async.commit_group;");

    for (int ch = 0; ch < 16; ch++) {
        if (ch < 15) {
            int k0 = (ch + 1) * 32;
            int boff = ((ch + 1) & 1) * 5120;
            #pragma unroll
            for (int i = 0; i < 2; i++) {
                cp16(xsa + (boff + srow[i]*40 + sc8[i]) * 2,
                     g.X + (size_t)(bm + srow[i]) * g.ldx + k0 + sc8[i], true);
                int n = bn + srow[i];
                int nc = n < g.N ? n : 0;
                cp16(wsa + (boff + srow[i]*40 + sc8[i]) * 2,
                     g.W + (size_t)nc * 512 + k0 + sc8[i], n < g.N);
            }
            asm volatile("cp.async.commit_group;");
            asm volatile("cp.async.wait_group 1;");
        } else {
            asm volatile("cp.async.wait_group 0;");
        }
        __syncthreads();

        const int bo = (ch & 1) * 5120;
        #pragma unroll
        for (int ks = 0; ks < 2; ks++) {
            const int kk = ks * 16;
            uint32_t a[2][4], bb[8][2];
            #pragma unroll
            for (int mt = 0; mt < 2; mt++)
                ldsm4(a[mt][0], a[mt][1], a[mt][2], a[mt][3],
                      xsa + (bo + (wm + 16*mt + lm_row)*40 + kk + 8*lm_hi) * 2);
            #pragma unroll
            for (int nt2 = 0; nt2 < 4; nt2++) {
                uint32_t r0, r1, r2, r3;
                ldsm4(r0, r1, r2, r3,
                      wsa + (bo + (wn + 16*nt2 + lm_row)*40 + kk + 8*lm_hi) * 2);
                bb[2*nt2][0]   = r0; bb[2*nt2][1]   = r2;
                bb[2*nt2+1][0] = r1; bb[2*nt2+1][1] = r3;
            }
            #pragma unroll
            for (int mt = 0; mt < 2; mt++)
                #pragma unroll
                for (int nt = 0; nt < 8; nt++)
                    mma_f16(c[mt][nt], a[mt][0], a[mt][1], a[mt][2], a[mt][3],
                            bb[nt][0], bb[nt][1]);
        }
        __syncthreads();
    }

    const int lq = lane >> 2;
    #pragma unroll
    for (int mt = 0; mt < 2; mt++)
        #pragma unroll
        for (int j = 0; j < 2; j++) {
            int row = bm + wm + 16 * mt + lq + 8 * j;
            const float* mrow = g.mul ? (g.mul + (size_t)row * g.ldmul) : (const float*)0;
            #pragma unroll
            for (int nt = 0; nt < 8; nt++) {
                int col = bn + wn + 8 * nt + 2 * lr;
                if (col < g.N) {
                    float v0 = c[mt][nt][2 * j]     + g.bias[col];
                    float v1 = c[mt][nt][2 * j + 1] + g.bias[col + 1];
                    if (mrow) { v0 *= mrow[col]; v1 *= mrow[col + 1]; }
                    if (g.outHalf) {
                        __half2 hv = __floats2half2_rn(v0 * g.osc, v1 * g.osc);
                        *(__half2*)((__half*)g.C + (size_t)row * g.ldc + col) = hv;
                    } else {
                        *(float2*)((float*)g.C + (size_t)row * g.ldc + col) =
                            make_float2(v0, v1);
                    }
                }
            }
        }
}

// ---------------- depthwise conv along seq (K=9, pad 4); half output ----------
__global__ void dwconv_kernel(const float* __restrict__ hid, const float* __restrict__ dw)
{
    int idx = blockIdx.x * blockDim.x + threadIdx.x;
    int c = idx & (AA - 1);
    int m = idx >> 9;
    int b = m >> 11, s = m & (SS - 1);
    float acc = 0.f;
    #pragma unroll
    for (int k = 0; k < KW; k++) {
        int s2 = s + k - KW / 2;
        if (s2 >= 0 && s2 < SS)
            acc = fmaf(hid[(size_t)(b * SS + s2) * HIDD + AA + c], dw[c * KW + k], acc);
    }
    g_dwh[idx] = __float2half_rn(acc);
}

// ---------------- conv_out with inline softmax over K=9 ----------------
__global__ void convout_kernel(float* __restrict__ out)
{
    int idx = blockIdx.x * blockDim.x + threadIdx.x;
    int c = idx & (AA - 1);
    int m = idx >> 9;
    int b = m >> 11, s = m & (SS - 1);
    int h = c >> 6;
    const float* lg = g_ckl + (size_t)m * (NH * KW) + h * KW;
    float l[KW], mx = -INFINITY;
    #pragma unroll
    for (int k = 0; k < KW; k++) { l[k] = lg[k]; mx = fmaxf(mx, l[k]); }
    float sum = 0.f;
    #pragma unroll
    for (int k = 0; k < KW; k++) { l[k] = fast_exp(l[k] - mx); sum += l[k]; }
    float acc = 0.f;
    #pragma unroll
    for (int k = 0; k < KW; k++) {
        int s2 = s + k - KW / 2;
        if (s2 >= 0 && s2 < SS)
            acc = fmaf(g_col[(size_t)(b * SS + s2) * AA + c], l[k], acc);
    }
    out[(size_t)m * HIDD + AA + c] = acc / sum;
}

// ---------------- flash attention: all-fp16 mma + fast_exp --------------------
// 128 q-rows/CTA, 8 warps (16 rows each); Q frags hoisted to registers;
// K via ldmatrix (no-trans), V via ldmatrix.trans; P register-forwarded to PV.
__global__ __launch_bounds__(256, 2)
void attn_kernel(float* __restrict__ out)
{
    extern __shared__ __align__(16) __half sma[];
    __half* Qs = sma;                 // [128][72]
    __half* Ks = Qs + 128 * 72;       // [128][72]
    __half* Vh = Ks + 128 * 72;       // [128][72]

    const int tid  = threadIdx.x;
    const int lane = tid & 31, wid = tid >> 5;
    const int lq = lane >> 2, lr = lane & 3;
    const int q0 = blockIdx.x * 128;
    const int h = blockIdx.y & (NH - 1), b = blockIdx.y >> 3;

    const __half* Qg = g_qh + (size_t)(b * SS) * AA + h * HD;
    const __half* Kg = g_kh + (size_t)(b * SS) * AA + h * HD;
    const __half* Vg = g_vh + (size_t)(b * SS) * AA + h * HD;

    const uint32_t qsa = (uint32_t)__cvta_generic_to_shared(Qs);
    const uint32_t ksa = (uint32_t)__cvta_generic_to_shared(Ks);
    const uint32_t vha = (uint32_t)__cvta_generic_to_shared(Vh);

    const int lm_row = (lane & 7) + 8 * ((lane >> 3) & 1);
    const int lm_hi  = lane >> 4;

    // load Q tile (128 rows x 64 halfs = 8 chunks of 16B per row; 4 iters)
    #pragma unroll
    for (int i = 0; i < 4; i++) {
        int fl = tid + i * 256;
        int row = fl >> 3, c8 = (fl & 7) << 3;
        cp16(qsa + (row * 72 + c8) * 2,
             Qg + (size_t)(q0 + row) * AA + c8, true);
    }
    asm volatile("cp.async.commit_group;");
    asm volatile("cp.async.wait_group 0;");
    __syncthreads();

    // hoist Q fragments (loop-invariant): 4 k16-steps
    uint32_t qa[4][4];
    #pragma unroll
    for (int ks = 0; ks < 4; ks++)
        ldsm4(qa[ks][0], qa[ks][1], qa[ks][2], qa[ks][3],
              qsa + ((wid * 16 + lm_row) * 72 + 16 * ks + 8 * lm_hi) * 2);

    float o[8][4];
    #pragma unroll
    for (int nt = 0; nt < 8; nt++)
        #pragma unroll
        for (int j = 0; j < 4; j++) o[nt][j] = 0.f;
    float mr[2] = {-INFINITY, -INFINITY}, l_[2] = {0.f, 0.f};

    const int arow = wid * 16 + lq;

    for (int kt = 0; kt < 16; kt++) {
        __syncthreads();
        #pragma unroll
        for (int i = 0; i < 4; i++) {
            int fl = tid + i * 256;
            int row = fl >> 3, c8 = (fl & 7) << 3;
            size_t gidx = (size_t)(kt * 128 + row) * AA + c8;
            cp16(ksa + (row * 72 + c8) * 2, Kg + gidx, true);
            cp16(vha + (row * 72 + c8) * 2, Vg + gidx, true);
        }
        asm volatile("cp.async.commit_group;");
        asm volatile("cp.async.wait_group 0;");
        __syncthreads();

        #pragma unroll
        for (int h2 = 0; h2 < 2; h2++) {
            // S = Q K^T for 64 keys (8 n-tiles)
            float s[8][4];
            #pragma unroll
            for (int nt = 0; nt < 8; nt++)
                #pragma unroll
                for (int j = 0; j < 4; j++) s[nt][j] = 0.f;

            #pragma unroll
            for (int ks = 0; ks < 4; ks++) {
                const int kk = ks * 16;
                uint32_t bb[8][2];
                #pragma unroll
                for (int nt2 = 0; nt2 < 4; nt2++) {
                    uint32_t r0, r1, r2, r3;
                    ldsm4(r0, r1, r2, r3,
                          ksa + ((h2*64 + 16*nt2 + lm_row) * 72 + kk + 8*lm_hi) * 2);
                    bb[2*nt2][0]   = r0; bb[2*nt2][1]   = r2;
                    bb[2*nt2+1][0] = r1; bb[2*nt2+1][1] = r3;
                }
                #pragma unroll
                for (int nt = 0; nt < 8; nt++)
                    mma_f16(s[nt], qa[ks][0], qa[ks][1], qa[ks][2], qa[ks][3],
                            bb[nt][0], bb[nt][1]);
            }

            // online softmax (thread rows arow, arow+8; 4 lanes/row)
            #pragma unroll
            for (int j = 0; j < 2; j++) {
                float tm = -INFINITY;
                #pragma unroll
                for (int nt = 0; nt < 8; nt++)
                    tm = fmaxf(tm, fmaxf(s[nt][2*j], s[nt][2*j+1]));
                tm = fmaxf(tm, __shfl_xor_sync(0xffffffffu, tm, 1));
                tm = fmaxf(tm, __shfl_xor_sync(0xffffffffu, tm, 2));
                float mnew = fmaxf(mr[j], tm);
                float alpha = fast_exp(mr[j] - mnew);
                float sum = 0.f;
                #pragma unroll
                for (int nt = 0; nt < 8; nt++) {
                    float e0 = fast_exp(s[nt][2*j]   - mnew);
                    float e1 = fast_exp(s[nt][2*j+1] - mnew);
                    sum += e0 + e1;
                    s[nt][2*j]   = e0;
                    s[nt][2*j+1] = e1;
                }
                sum += __shfl_xor_sync(0xffffffffu, sum, 1);
                sum += __shfl_xor_sync(0xffffffffu, sum, 2);
                l_[j] = l_[j] * alpha + sum;
                mr[j] = mnew;
                #pragma unroll
                for (int nt = 0; nt < 8; nt++) {
                    o[nt][2*j]   *= alpha;
                    o[nt][2*j+1] *= alpha;
                }
            }

            // O += P @ V : P accum layout == f16 A-frag layout
            #pragma unroll
            for (int t = 0; t < 4; t++) {
                uint32_t pa0 = packh2(s[2*t][0],   s[2*t][1]);
                uint32_t pa1 = packh2(s[2*t][2],   s[2*t][3]);
                uint32_t pa2 = packh2(s[2*t+1][0], s[2*t+1][1]);
                uint32_t pa3 = packh2(s[2*t+1][2], s[2*t+1][3]);
                const int kbase = h2 * 64 + 16 * t;
                #pragma unroll
                for (int ntp = 0; ntp < 4; ntp++) {
                    uint32_t addr = vha +
                        ((kbase + lm_row) * 72 + 8 * (2 * ntp + lm_hi)) * 2;
                    uint32_t b0, b1, b2, b3;
                    ldsm4t(b0, b1, b2, b3, addr);
                    mma_f16(o[2*ntp],     pa0, pa1, pa2, pa3, b0, b1);
                    mma_f16(o[2*ntp + 1], pa0, pa1, pa2, pa3, b2, b3);
                }
            }
        }
    }

    // epilogue
    #pragma unroll
    for (int j = 0; j < 2; j++) {
        float inv = 1.f / l_[j];
        size_t row = (size_t)(b * SS + q0 + arow + 8 * j);
        #pragma unroll
        for (int nt = 0; nt < 8; nt++) {
            int col = h * HD + 8 * nt + 2 * lr;
            *(float2*)&out[row * HIDD + col] =
                make_float2(o[nt][2*j] * inv, o[nt][2*j+1] * inv);
        }
    }
}

// ---------------- launch ----------------
extern "C" void kernel_launch(void* const* d_in, const int* in_sizes, int n_in,
                              void* d_out, int out_size)
{
    const float* hid  = (const float*)d_in[0];
    const float* Wq   = (const float*)d_in[1];
    const float* bq   = (const float*)d_in[2];
    const float* Wk   = (const float*)d_in[3];
    const float* bk   = (const float*)d_in[4];
    const float* Wv   = (const float*)d_in[5];
    const float* bv   = (const float*)d_in[6];
    const float* dww  = (const float*)d_in[7];
    const float* pww  = (const float*)d_in[8];
    const float* sepb = (const float*)d_in[9];
    const float* Wck  = (const float*)d_in[10];
    const float* bck  = (const float*)d_in[11];
    const float* Wco  = (const float*)d_in[12];
    const float* bco  = (const float*)d_in[13];
    float* out = (float*)d_out;

    __half *qhp, *khp, *vhp, *dwhp, *cahp, *hidhp, *whp;
    float *colp, *cklp;
    cudaGetSymbolAddress((void**)&qhp,   g_qh);
    cudaGetSymbolAddress((void**)&khp,   g_kh);
    cudaGetSymbolAddress((void**)&vhp,   g_vh);
    cudaGetSymbolAddress((void**)&dwhp,  g_dwh);
    cudaGetSymbolAddress((void**)&cahp,  g_cah);
    cudaGetSymbolAddress((void**)&hidhp, g_hidh);
    cudaGetSymbolAddress((void**)&whp,   g_wh);
    cudaGetSymbolAddress((void**)&colp,  g_col);
    cudaGetSymbolAddress((void**)&cklp,  g_ckl);

    const int GEMM_SMEM = 4 * 5120 * 2;     // 40960
    const int ATTN_SMEM = 3 * 128 * 72 * 2; // 55296
    cudaFuncSetAttribute(gemm_kernel, cudaFuncAttributeMaxDynamicSharedMemorySize, GEMM_SMEM);
    cudaFuncSetAttribute(attn_kernel, cudaFuncAttributeMaxDynamicSharedMemorySize, ATTN_SMEM);

    const int WSZ = AA * AA;

    CArgs ca;
    ca.s[0] = { hid, hidhp,          MM * HIDD / 4 };
    ca.s[1] = { Wq,  whp + 0 * WSZ,  WSZ / 4 };
    ca.s[2] = { Wk,  whp + 1 * WSZ,  WSZ / 4 };
    ca.s[3] = { Wv,  whp + 2 * WSZ,  WSZ / 4 };
    ca.s[4] = { Wco, whp + 3 * WSZ,  WSZ / 4 };
    ca.s[5] = { pww, whp + 4 * WSZ,  WSZ / 4 };
    ca.s[6] = { Wck, whp + 5 * WSZ,  NH * KW * AA / 4 };
    cvt_kernel<<<dim3(512, 1, 7), 256>>>(ca);

    GArgs g1;   // q (pre-scaled 1/8), k, v as half; col as f32
    g1.s[0] = { hidhp,      whp + 0*WSZ, bq,  nullptr, qhp,  HIDD, 0, AA, AA, 1, 0.125f };
    g1.s[1] = { hidhp,      whp + 1*WSZ, bk,  nullptr, khp,  HIDD, 0, AA, AA, 1, 1.f };
    g1.s[2] = { hidhp,      whp + 2*WSZ, bv,  nullptr, vhp,  HIDD, 0, AA, AA, 1, 1.f };
    g1.s[3] = { hidhp + AA, whp + 3*WSZ, bco, nullptr, colp, HIDD, 0, AA, AA, 0, 1.f };
    gemm_kernel<<<dim3(4, 64, 4), 256, GEMM_SMEM>>>(g1);

    dwconv_kernel<<<MM * AA / 256, 256>>>(hid, dww);

    GArgs g2;   // conv_attn = (dw @ pw^T + sep_b) * hs_conv  -> half
    g2.s[0] = { dwhp, whp + 4*WSZ, sepb, hid + AA, cahp, AA, HIDD, AA, AA, 1, 1.f };
    gemm_kernel<<<dim3(4, 64, 1), 256, GEMM_SMEM>>>(g2);

    GArgs g3;   // ckl logits (N=72) -> f32
    g3.s[0] = { cahp, whp + 5*WSZ, bck, nullptr, cklp, AA, 0, NH*KW, NH*KW, 0, 1.f };
    gemm_kernel<<<dim3(1, 64, 1), 256, GEMM_SMEM>>>(g3);

    convout_kernel<<<MM * AA / 256, 256>>>(out);

    attn_kernel<<<dim3(SS / 128, BB * NH), 256, ATTN_SMEM>>>(out);
}